// round 10
// baseline (speedup 1.0000x reference)
#include <cuda_runtime.h>
#include <cuda_fp16.h>
#include <math.h>
#include <stdint.h>

#define Bn 16
#define Nn 2048
#define Dd 512
#define Mm 512
#define DT_C 0.01f

typedef __half hf;

// ------------------------- device scratch (no runtime alloc) ---------------
__device__ hf g_h1[(size_t)32768 * 512];   // 32MB  (K-RBF / field / enh)
__device__ hf g_h2[(size_t)8192 * 512];    // 8MB   (gelu)
__device__ hf g_ebh[(size_t)Bn * Dd * Nn]; // 32MB  embT  [b, d, t]
__device__ hf g_wh[4][512 * 512];          // 2MB   weight^T [n, k]
__device__ float g_field[(size_t)Bn * Mm * Dd]; // 16MB
__device__ float g_tmp2[(size_t)Bn * Mm * Dd];  // 16MB

// ------------------------- helpers -----------------------------------------
__device__ __forceinline__ uint32_t smem_u32(const void* p) {
    uint32_t a;
    asm("{ .reg .u64 t; cvta.to.shared.u64 t, %1; cvt.u32.u64 %0, t; }" : "=r"(a) : "l"(p));
    return a;
}
__device__ __forceinline__ uint32_t pack_hf2(float a, float b) {
    __half2 t = __floats2half2_rn(a, b);
    return *reinterpret_cast<uint32_t*>(&t);
}
__device__ __forceinline__ void cp16(uint32_t dst, const void* src) {
    asm volatile("cp.async.cg.shared.global [%0], [%1], 16;" :: "r"(dst), "l"(src));
}
__device__ __forceinline__ void cp_commit() {
    asm volatile("cp.async.commit_group;");
}
__device__ __forceinline__ void cp_wait2() {
    asm volatile("cp.async.wait_group 2;");
}
__device__ __forceinline__ void ldm_x4(uint32_t* r, uint32_t a) {
    asm volatile("ldmatrix.sync.aligned.m8n8.x4.shared.b16 {%0,%1,%2,%3}, [%4];"
                 : "=r"(r[0]), "=r"(r[1]), "=r"(r[2]), "=r"(r[3]) : "r"(a));
}
__device__ __forceinline__ void ldm_x2(uint32_t* r, uint32_t a) {
    asm volatile("ldmatrix.sync.aligned.m8n8.x2.shared.b16 {%0,%1}, [%2];"
                 : "=r"(r[0]), "=r"(r[1]) : "r"(a));
}
__device__ __forceinline__ void mma_f16(float* c, const uint32_t* a, const uint32_t* b) {
    asm volatile(
        "mma.sync.aligned.m16n8k16.row.col.f32.f16.f16.f32 "
        "{%0,%1,%2,%3}, {%4,%5,%6,%7}, {%8,%9}, {%0,%1,%2,%3};"
        : "+f"(c[0]), "+f"(c[1]), "+f"(c[2]), "+f"(c[3])
        : "r"(a[0]), "r"(a[1]), "r"(a[2]), "r"(a[3]), "r"(b[0]), "r"(b[1]));
}

// ------------------------- HMMA GEMM (fp16, single-pass) --------------------
// D[128,128] CTA tile; 8 warps 2(M)x4(N), warp tile 64x32.
// A, B single fp16 K-major. SMEM/stage: A 16K | B 16K = 32KB; 3 stages = 96KB
// -> 2 CTAs/SM.
#define STAGE_B 32768u
#define SMEM_SZ (3 * 32768)

// RESF: add f32 residual from resp; RESH: add fp16 residual from resph.
template <bool GELU, bool RESF, bool RESH, bool WF32, bool WHALF>
__global__ __launch_bounds__(256, 2)
void k_gemm_mma(const hf* __restrict__ A, size_t aRS, size_t aBS,
                const hf* __restrict__ B, size_t bRS, size_t bBS,
                const float* __restrict__ bias, const float* __restrict__ resp,
                const hf* __restrict__ resph,
                float* __restrict__ C, hf* __restrict__ Ch,
                size_t cBS, int Kdim)
{
    extern __shared__ char smem[];
    const uint32_t sb = smem_u32(smem);
    const int t = threadIdx.x;
    const int wid = t >> 5;
    const int lane = t & 31;
    const int warp_m = wid & 1;   // 2 warps over M (64 rows each)
    const int warp_n = wid >> 1;  // 4 warps over N (32 cols each)

    const int m0 = blockIdx.x * 128;
    const int n0 = blockIdx.y * 128;
    const int z = blockIdx.z;

    const hf* pA = A + (size_t)z * aBS;
    const hf* pB = B + (size_t)z * bBS;

    const int NC = Kdim >> 6;

    auto load_chunk = [&](int c) {
        const uint32_t buf = sb + (uint32_t)(c % 3) * STAGE_B;
        const int k0 = c << 6;
#pragma unroll
        for (int i = 0; i < 4; i++) {
            int id = t + i * 256;
            int row = id >> 3;
            int seg = id & 7;
            uint32_t soff = (uint32_t)row * 128 + (uint32_t)((seg * 16) ^ ((row & 7) << 4));
            cp16(buf + soff,         pA + (size_t)(m0 + row) * aRS + k0 + seg * 8);
            cp16(buf + 16384 + soff, pB + (size_t)(n0 + row) * bRS + k0 + seg * 8);
        }
    };

    load_chunk(0); cp_commit();
    load_chunk(1); cp_commit();
    load_chunk(2); cp_commit();

    // fragment address precomputation
    const int rowA = warp_m * 64 + (lane & 15);
    const uint32_t maskA = (uint32_t)(rowA & 7) << 4;
    const uint32_t kbA = (uint32_t)(lane >> 4) * 16;
    const int rowB = warp_n * 32 + (lane & 7);
    const uint32_t maskB = (uint32_t)(rowB & 7) << 4;
    const uint32_t kbB = (uint32_t)((lane >> 3) & 1) * 16;

    float acc[4][4][4] = {};

    for (int c = 0; c < NC; c++) {
        cp_wait2();
        __syncthreads();
        const uint32_t buf = sb + (uint32_t)(c % 3) * STAGE_B;
        const uint32_t aBase = buf + (uint32_t)rowA * 128;
        const uint32_t bBase = buf + 16384 + (uint32_t)rowB * 128;

#pragma unroll
        for (int k16 = 0; k16 < 4; k16++) {
            const uint32_t koffA = ((uint32_t)k16 * 32 + kbA) ^ maskA;
            const uint32_t koffB = ((uint32_t)k16 * 32 + kbB) ^ maskB;
            uint32_t ah[4][4], bh[4][2];
#pragma unroll
            for (int mi = 0; mi < 4; mi++)
                ldm_x4(ah[mi], aBase + mi * 2048 + koffA);
#pragma unroll
            for (int ni = 0; ni < 4; ni++)
                ldm_x2(bh[ni], bBase + ni * 1024 + koffB);
#pragma unroll
            for (int mi = 0; mi < 4; mi++)
#pragma unroll
                for (int ni = 0; ni < 4; ni++)
                    mma_f16(acc[mi][ni], ah[mi], bh[ni]);
        }
        __syncthreads();
        if (c + 3 < NC) load_chunk(c + 3);
        cp_commit();
    }

    // ------------------------- epilogue -------------------------
    const int rbase = m0 + warp_m * 64 + (lane >> 2);
    const int cbase = n0 + warp_n * 32 + (lane & 3) * 2;
#pragma unroll
    for (int mi = 0; mi < 4; mi++) {
#pragma unroll
        for (int half = 0; half < 2; half++) {
            const int row = rbase + mi * 16 + half * 8;
#pragma unroll
            for (int ni = 0; ni < 4; ni++) {
                const int col = cbase + ni * 8;
                float v0 = acc[mi][ni][half * 2 + 0];
                float v1 = acc[mi][ni][half * 2 + 1];
                if (bias) {
                    v0 += __ldg(&bias[col]);
                    v1 += __ldg(&bias[col + 1]);
                }
                if (GELU) {
                    float x3 = v0 * v0 * v0;
                    v0 = 0.5f * v0 * (1.0f + tanhf(0.7978845608028654f * (v0 + 0.044715f * x3)));
                    x3 = v1 * v1 * v1;
                    v1 = 0.5f * v1 * (1.0f + tanhf(0.7978845608028654f * (v1 + 0.044715f * x3)));
                }
                const size_t o = (size_t)z * cBS + (size_t)row * 512 + col;
                if (RESF) {
                    float2 q = *(const float2*)(resp + o);
                    v0 += q.x; v1 += q.y;
                }
                if (RESH) {
                    uint32_t rv = *(const uint32_t*)(resph + o);
                    __half2 rh = *reinterpret_cast<__half2*>(&rv);
                    v0 += __half2float(rh.x);
                    v1 += __half2float(rh.y);
                }
                if (WF32)
                    *(float2*)(C + o) = make_float2(v0, v1);
                if (WHALF)
                    *(uint32_t*)(Ch + o) = pack_hf2(v0, v1);
            }
        }
    }
}

// ------------------------- prep / elementwise kernels ----------------------
// Transpose + fp16: src [R, C] f32 -> dst [C, R] fp16
__global__ void k_thalf(const float* __restrict__ src, hf* __restrict__ dh,
                        int R, int C, size_t sBS, size_t dBS)
{
    __shared__ float tile[32][33];
    const int tx = threadIdx.x, ty = threadIdx.y;
    const int c0 = blockIdx.x * 32, r0 = blockIdx.y * 32;
    const int z = blockIdx.z;
    src += (size_t)z * sBS; dh += (size_t)z * dBS;
#pragma unroll
    for (int i = 0; i < 4; i++)
        tile[ty + i * 8][tx] = src[(size_t)(r0 + ty + i * 8) * C + c0 + tx];
    __syncthreads();
#pragma unroll
    for (int i = 0; i < 4; i++) {
        float v = tile[tx][ty + i * 8];
        dh[(size_t)(c0 + ty + i * 8) * R + r0 + tx] = __float2half_rn(v);
    }
}

// Fused 4-weight transpose+fp16 (one launch, z selects weight)
__global__ void k_thalf4(const float* __restrict__ s0, const float* __restrict__ s1,
                         const float* __restrict__ s2, const float* __restrict__ s3,
                         hf* __restrict__ dh)
{
    __shared__ float tile[32][33];
    const int tx = threadIdx.x, ty = threadIdx.y;
    const int c0 = blockIdx.x * 32, r0 = blockIdx.y * 32;
    const int z = blockIdx.z;
    const float* src = (z == 0) ? s0 : (z == 1) ? s1 : (z == 2) ? s2 : s3;
    dh += (size_t)z * 262144;
#pragma unroll
    for (int i = 0; i < 4; i++)
        tile[ty + i * 8][tx] = src[(size_t)(r0 + ty + i * 8) * 512 + c0 + tx];
    __syncthreads();
#pragma unroll
    for (int i = 0; i < 4; i++) {
        float v = tile[tx][ty + i * 8];
        dh[(size_t)(c0 + ty + i * 8) * 512 + r0 + tx] = __float2half_rn(v);
    }
}

// K_rbf -> single fp16
__global__ void k_rbf_half(const float* __restrict__ pos, const float* __restrict__ sigma,
                           hf* __restrict__ kh)
{
    size_t lin = (size_t)blockIdx.x * 256 + threadIdx.x; // < 16*512*512
    int t4 = (int)(lin & 511);
    int m = (int)((lin >> 9) & 511);
    int b = (int)(lin >> 18);
    float s = __ldg(sigma);
    float inv = 1.0f / (2.0f * s * s);
    float gm = (float)m * (1.0f / 511.0f);
    float4 p = *(const float4*)(pos + (size_t)b * Nn + t4 * 4);
    float v0 = __expf(-(gm - p.x) * (gm - p.x) * inv);
    float v1 = __expf(-(gm - p.y) * (gm - p.y) * inv);
    float v2 = __expf(-(gm - p.z) * (gm - p.z) * inv);
    float v3 = __expf(-(gm - p.w) * (gm - p.w) * inv);
    size_t o = ((size_t)b * 512 + m) * 2048 + t4 * 4;
    uint2 hh;
    hh.x = pack_hf2(v0, v1); hh.y = pack_hf2(v2, v3);
    *(uint2*)(kh + o) = hh;
}

// Head mixing -> single fp16
__global__ void k_headmix_half(const float* __restrict__ alpha,
                               const float* __restrict__ field,
                               hf* __restrict__ oh)
{
    size_t i2 = (size_t)blockIdx.x * 256 + threadIdx.x; // < 8192*512/2
    size_t idx = i2 * 2;
    int dcol = (int)(idx & 511);
    int h = dcol >> 6, dd = dcol & 63;
    size_t base = idx - dcol;
    float s0 = 0.0f, s1 = 0.0f;
#pragma unroll
    for (int k = 0; k < 8; k++) {
        float a = __ldg(&alpha[h * 8 + k]);
        const float* f = field + base + k * 64 + dd;
        s0 = fmaf(a, f[0], s0);
        s1 = fmaf(a, f[1], s1);
    }
    *(uint32_t*)(oh + idx) = pack_hf2(s0, s1);
}

template <bool HOUT>
__global__ __launch_bounds__(256)
void k_diffuse3(const float* __restrict__ in, float* __restrict__ out,
                const float* __restrict__ coef, hf* __restrict__ oh)
{
    __shared__ float s[512 * 8];
    const int t = threadIdx.x;
    const int b = blockIdx.x >> 6;
    const int d0 = (blockIdx.x & 63) * 8;
    const int dl = t & 7;
    const size_t gbase = ((size_t)b * Mm) * Dd + d0;
    const float c = DT_C * __ldg(&coef[d0 + dl]);
#pragma unroll
    for (int i = 0; i < 16; i++) {
        int idx = t + i * 256;
        s[idx] = in[gbase + (size_t)(idx >> 3) * Dd + dl];
    }
    __syncthreads();
#pragma unroll
    for (int step = 0; step < 3; step++) {
        float nv[16];
#pragma unroll
        for (int i = 0; i < 16; i++) {
            int idx = t + i * 256;
            int m = idx >> 3;
            float v = s[idx];
            float l = (m > 0) ? s[idx - 8] : v;
            float r = (m < 511) ? s[idx + 8] : v;
            nv[i] = fmaf(c, l + r - 2.0f * v, v);
        }
        __syncthreads();
#pragma unroll
        for (int i = 0; i < 16; i++) s[t + i * 256] = nv[i];
        __syncthreads();
    }
#pragma unroll
    for (int i = 0; i < 16; i++) {
        int idx = t + i * 256;
        size_t g = gbase + (size_t)(idx >> 3) * Dd + dl;
        float v = s[idx];
        out[g] = v;
        if (HOUT) oh[g] = __float2half_rn(v);
    }
}

// sample + residual + LN1 -> fp16 (enh)
__global__ __launch_bounds__(128)
void k_sample_ln(const float* __restrict__ pos, const float* __restrict__ emb,
                 const float* __restrict__ field,
                 const float* __restrict__ gam, const float* __restrict__ bet,
                 hf* __restrict__ oh)
{
    __shared__ float ssum[4], ssq[4], sstat[2];
    int row = blockIdx.x;
    int b = row >> 11;
    float p = __ldg(&pos[row]);
    float u = fminf(fmaxf(p, 0.0f), 1.0f) * (float)(Mm - 1);
    int i0 = (int)u;
    if (i0 > Mm - 2) i0 = Mm - 2;
    float w = u - (float)i0;

    const float* f0 = field + ((size_t)b * Mm + i0) * Dd;
    int t = threadIdx.x;
    int d0 = t * 4;
    float4 a = *(const float4*)(f0 + d0);
    float4 bb = *(const float4*)(f0 + Dd + d0);
    float4 e = *(const float4*)(emb + (size_t)row * Dd + d0);
    float x[4];
    x[0] = fmaf(w, bb.x - a.x, a.x) + e.x;
    x[1] = fmaf(w, bb.y - a.y, a.y) + e.y;
    x[2] = fmaf(w, bb.z - a.z, a.z) + e.z;
    x[3] = fmaf(w, bb.w - a.w, a.w) + e.w;
    float sum = x[0] + x[1] + x[2] + x[3];
    float sq = fmaf(x[0], x[0], fmaf(x[1], x[1], fmaf(x[2], x[2], x[3] * x[3])));
#pragma unroll
    for (int o = 16; o > 0; o >>= 1) {
        sum += __shfl_down_sync(0xffffffffu, sum, o);
        sq += __shfl_down_sync(0xffffffffu, sq, o);
    }
    int wd = t >> 5, ln = t & 31;
    if (ln == 0) { ssum[wd] = sum; ssq[wd] = sq; }
    __syncthreads();
    if (t == 0) {
        float S = ssum[0] + ssum[1] + ssum[2] + ssum[3];
        float Q = ssq[0] + ssq[1] + ssq[2] + ssq[3];
        float mu = S * (1.0f / Dd);
        float var = Q * (1.0f / Dd) - mu * mu;
        sstat[0] = mu;
        sstat[1] = rsqrtf(var + 1e-5f);
    }
    __syncthreads();
    float mu = sstat[0], inv = sstat[1];
    float4 g = *(const float4*)(gam + d0);
    float4 be = *(const float4*)(bet + d0);
    float y0 = (x[0] - mu) * inv * g.x + be.x;
    float y1 = (x[1] - mu) * inv * g.y + be.y;
    float y2 = (x[2] - mu) * inv * g.z + be.z;
    float y3 = (x[3] - mu) * inv * g.w + be.w;
    size_t o = (size_t)row * Dd + d0;
    uint2 hh;
    hh.x = pack_hf2(y0, y1); hh.y = pack_hf2(y2, y3);
    *(uint2*)(oh + o) = hh;
}

// final LN2 in-place on out (residual already included by Wout epilogue)
__global__ __launch_bounds__(128)
void k_ln2(const float* __restrict__ gam, const float* __restrict__ bet,
           float* __restrict__ out)
{
    __shared__ float ssum[4], ssq[4], sstat[2];
    int row = blockIdx.x;
    int t = threadIdx.x;
    int d0 = t * 4;
    size_t o = (size_t)row * Dd + d0;
    float4 a = *(const float4*)(out + o);
    float x[4] = {a.x, a.y, a.z, a.w};
    float sum = x[0] + x[1] + x[2] + x[3];
    float sq = fmaf(x[0], x[0], fmaf(x[1], x[1], fmaf(x[2], x[2], x[3] * x[3])));
#pragma unroll
    for (int s = 16; s > 0; s >>= 1) {
        sum += __shfl_down_sync(0xffffffffu, sum, s);
        sq += __shfl_down_sync(0xffffffffu, sq, s);
    }
    int wd = t >> 5, ln = t & 31;
    if (ln == 0) { ssum[wd] = sum; ssq[wd] = sq; }
    __syncthreads();
    if (t == 0) {
        float S = ssum[0] + ssum[1] + ssum[2] + ssum[3];
        float Q = ssq[0] + ssq[1] + ssq[2] + ssq[3];
        float mu = S * (1.0f / Dd);
        float var = Q * (1.0f / Dd) - mu * mu;
        sstat[0] = mu;
        sstat[1] = rsqrtf(var + 1e-5f);
    }
    __syncthreads();
    float mu = sstat[0], inv = sstat[1];
    float4 g = *(const float4*)(gam + d0);
    float4 be = *(const float4*)(bet + d0);
    *(float4*)(out + o) = make_float4(
        (x[0] - mu) * inv * g.x + be.x, (x[1] - mu) * inv * g.y + be.y,
        (x[2] - mu) * inv * g.z + be.z, (x[3] - mu) * inv * g.w + be.w);
}

// ---------------------------------------------------------------------------
extern "C" void kernel_launch(void* const* d_in, const int* in_sizes, int n_in,
                              void* d_out, int out_size)
{
    const float* emb   = (const float*)d_in[0];
    const float* pos   = (const float*)d_in[1];
    const float* sigma = (const float*)d_in[2];
    const float* alpha = (const float*)d_in[3];
    const float* w_int = (const float*)d_in[4];
    const float* b_int = (const float*)d_in[5];
    const float* dcoef = (const float*)d_in[6];
    const float* W1    = (const float*)d_in[7];
    const float* b1    = (const float*)d_in[8];
    const float* W2    = (const float*)d_in[9];
    const float* b2    = (const float*)d_in[10];
    const float* ecoef = (const float*)d_in[11];
    const float* ln1g  = (const float*)d_in[12];
    const float* ln1b  = (const float*)d_in[13];
    const float* Wout  = (const float*)d_in[14];
    const float* bout  = (const float*)d_in[15];
    const float* ln2g  = (const float*)d_in[16];
    const float* ln2b  = (const float*)d_in[17];
    float* out = (float*)d_out;

    hf *h1, *h2, *ebh, *wh;
    float *field, *tmp2;
    cudaGetSymbolAddress((void**)&h1, g_h1);
    cudaGetSymbolAddress((void**)&h2, g_h2);
    cudaGetSymbolAddress((void**)&ebh, g_ebh);
    cudaGetSymbolAddress((void**)&wh, g_wh);
    cudaGetSymbolAddress((void**)&field, g_field);
    cudaGetSymbolAddress((void**)&tmp2, g_tmp2);

    cudaFuncSetAttribute(k_gemm_mma<false, false, false, true, false>,
                         cudaFuncAttributeMaxDynamicSharedMemorySize, SMEM_SZ);
    cudaFuncSetAttribute(k_gemm_mma<false, true, false, true, false>,
                         cudaFuncAttributeMaxDynamicSharedMemorySize, SMEM_SZ);
    cudaFuncSetAttribute(k_gemm_mma<true, false, false, false, true>,
                         cudaFuncAttributeMaxDynamicSharedMemorySize, SMEM_SZ);
    cudaFuncSetAttribute(k_gemm_mma<false, false, true, true, false>,
                         cudaFuncAttributeMaxDynamicSharedMemorySize, SMEM_SZ);

    dim3 tT(32, 8);

    // weights^T fp16 (single fused launch)
    k_thalf4<<<dim3(16, 16, 4), tT>>>(w_int, W1, W2, Wout, wh);

    // embT fp16  [b, d, t]
    k_thalf<<<dim3(16, 64, 16), tT>>>(emb, ebh, Nn, Dd,
                                      (size_t)Nn * Dd, (size_t)Dd * Nn);

    // K-RBF fp16 into h1 (flat 16x512x2048)
    k_rbf_half<<<16384, 256>>>(pos, sigma, h1);

    // 1) field = K @ emb^T'   (batched, Kdim=2048)
    k_gemm_mma<false, false, false, true, false><<<dim3(4, 4, 16), 256, SMEM_SZ>>>(
        h1, 2048, (size_t)512 * 2048,
        ebh, 2048, (size_t)512 * 2048,
        nullptr, nullptr, nullptr, field, nullptr, (size_t)512 * 512, 2048);

    // 2) head mixing -> h1 (fp16)
    k_headmix_half<<<8192, 256>>>(alpha, field, h1);

    // 3) tmp2 = field + mix @ w_int + b_int
    k_gemm_mma<false, true, false, true, false><<<dim3(64, 4, 1), 256, SMEM_SZ>>>(
        h1, 512, 0, wh + 0 * 262144, 512, 0,
        b_int, field, nullptr, tmp2, nullptr, 0, 512);

    // 4) diffusion x3 -> field (+ fp16)
    k_diffuse3<true><<<Bn * 64, 256>>>(tmp2, field, dcoef, h1);

    // 5) gelu(field @ W1 + b1) -> h2 (fp16 only)
    k_gemm_mma<true, false, false, false, true><<<dim3(64, 4, 1), 256, SMEM_SZ>>>(
        h1, 512, 0, wh + 1 * 262144, 512, 0,
        b1, nullptr, nullptr, nullptr, h2, 0, 512);

    // 6) tmp2 = field + gelu @ W2 + b2
    k_gemm_mma<false, true, false, true, false><<<dim3(64, 4, 1), 256, SMEM_SZ>>>(
        h2, 512, 0, wh + 2 * 262144, 512, 0,
        b2, field, nullptr, tmp2, nullptr, 0, 512);

    // 7) diffusion x3 -> field
    k_diffuse3<false><<<Bn * 64, 256>>>(tmp2, field, ecoef, nullptr);

    // 8) enh = LN1(sample(field) + emb) -> h1 (fp16)
    k_sample_ln<<<Bn * Nn, 128>>>(pos, emb, field, ln1g, ln1b, h1);

    // 9) out = enh @ Wout + bout + enh   (residual fused in epilogue)
    k_gemm_mma<false, false, true, true, false><<<dim3(256, 4, 1), 256, SMEM_SZ>>>(
        h1, 512, 0, wh + 3 * 262144, 512, 0,
        bout, nullptr, h1, out, nullptr, 0, 512);

    // 10) out = LN2(out)
    k_ln2<<<Bn * Nn, 128>>>(ln2g, ln2b, out);
}

// round 11
// speedup vs baseline: 1.0289x; 1.0289x over previous
#include <cuda_runtime.h>
#include <cuda_fp16.h>
#include <math.h>
#include <stdint.h>

#define Bn 16
#define Nn 2048
#define Dd 512
#define Mm 512
#define DT_C 0.01f

typedef __half hf;

// ------------------------- device scratch (no runtime alloc) ---------------
__device__ hf g_h1[(size_t)32768 * 512];   // 32MB  (K-RBF -> gelu -> enh)
__device__ hf g_h2[(size_t)8192 * 512];    // 8MB   (field fp16)
__device__ hf g_ebh[(size_t)Bn * Dd * Nn]; // 32MB  embT [b,d,t]; later pre-LN2 fp16
__device__ hf g_wh[4][512 * 512];          // 2MB   [0]=folded W', [1..3]=W1,W2,Wout^T
__device__ float g_field[(size_t)Bn * Mm * Dd]; // 16MB
__device__ float g_tmp2[(size_t)Bn * Mm * Dd];  // 16MB

// ------------------------- helpers -----------------------------------------
__device__ __forceinline__ uint32_t smem_u32(const void* p) {
    uint32_t a;
    asm("{ .reg .u64 t; cvta.to.shared.u64 t, %1; cvt.u32.u64 %0, t; }" : "=r"(a) : "l"(p));
    return a;
}
__device__ __forceinline__ uint32_t pack_hf2(float a, float b) {
    __half2 t = __floats2half2_rn(a, b);
    return *reinterpret_cast<uint32_t*>(&t);
}
__device__ __forceinline__ void cp16(uint32_t dst, const void* src) {
    asm volatile("cp.async.cg.shared.global [%0], [%1], 16;" :: "r"(dst), "l"(src));
}
__device__ __forceinline__ void cp_commit() {
    asm volatile("cp.async.commit_group;");
}
__device__ __forceinline__ void cp_wait1() {
    asm volatile("cp.async.wait_group 1;");
}
__device__ __forceinline__ void ldm_x4(uint32_t* r, uint32_t a) {
    asm volatile("ldmatrix.sync.aligned.m8n8.x4.shared.b16 {%0,%1,%2,%3}, [%4];"
                 : "=r"(r[0]), "=r"(r[1]), "=r"(r[2]), "=r"(r[3]) : "r"(a));
}
__device__ __forceinline__ void ldm_x2(uint32_t* r, uint32_t a) {
    asm volatile("ldmatrix.sync.aligned.m8n8.x2.shared.b16 {%0,%1}, [%2];"
                 : "=r"(r[0]), "=r"(r[1]) : "r"(a));
}
__device__ __forceinline__ void mma_f16(float* c, const uint32_t* a, const uint32_t* b) {
    asm volatile(
        "mma.sync.aligned.m16n8k16.row.col.f32.f16.f16.f32 "
        "{%0,%1,%2,%3}, {%4,%5,%6,%7}, {%8,%9}, {%0,%1,%2,%3};"
        : "+f"(c[0]), "+f"(c[1]), "+f"(c[2]), "+f"(c[3])
        : "r"(a[0]), "r"(a[1]), "r"(a[2]), "r"(a[3]), "r"(b[0]), "r"(b[1]));
}

// ------------------------- HMMA GEMM (fp16, single-pass, 2-stage) -----------
// D[128,128] CTA tile; 8 warps 2(M)x4(N), warp tile 64x32.
// A, B single fp16 K-major. SMEM/stage: A 16K | B 16K = 32KB; 2 stages = 64KB
// -> 2 CTAs/SM.
#define STAGE_B 32768u
#define SMEM_SZ (2 * 32768)

// RESF: add f32 residual from resp; RESH: add fp16 residual from resph.
template <bool GELU, bool RESF, bool RESH, bool WF32, bool WHALF>
__global__ __launch_bounds__(256, 2)
void k_gemm_mma(const hf* __restrict__ A, size_t aRS, size_t aBS,
                const hf* __restrict__ B, size_t bRS, size_t bBS,
                const float* __restrict__ bias, const float* __restrict__ resp,
                const hf* __restrict__ resph,
                float* __restrict__ C, hf* __restrict__ Ch,
                size_t cBS, int Kdim)
{
    extern __shared__ char smem[];
    const uint32_t sb = smem_u32(smem);
    const int t = threadIdx.x;
    const int wid = t >> 5;
    const int lane = t & 31;
    const int warp_m = wid & 1;   // 2 warps over M (64 rows each)
    const int warp_n = wid >> 1;  // 4 warps over N (32 cols each)

    const int m0 = blockIdx.x * 128;
    const int n0 = blockIdx.y * 128;
    const int z = blockIdx.z;

    const hf* pA = A + (size_t)z * aBS;
    const hf* pB = B + (size_t)z * bBS;

    const int NC = Kdim >> 6;

    auto load_chunk = [&](int c) {
        const uint32_t buf = sb + (uint32_t)(c & 1) * STAGE_B;
        const int k0 = c << 6;
#pragma unroll
        for (int i = 0; i < 4; i++) {
            int id = t + i * 256;
            int row = id >> 3;
            int seg = id & 7;
            uint32_t soff = (uint32_t)row * 128 + (uint32_t)((seg * 16) ^ ((row & 7) << 4));
            cp16(buf + soff,         pA + (size_t)(m0 + row) * aRS + k0 + seg * 8);
            cp16(buf + 16384 + soff, pB + (size_t)(n0 + row) * bRS + k0 + seg * 8);
        }
    };

    load_chunk(0); cp_commit();
    if (NC > 1) { load_chunk(1); cp_commit(); }

    // fragment address precomputation
    const int rowA = warp_m * 64 + (lane & 15);
    const uint32_t maskA = (uint32_t)(rowA & 7) << 4;
    const uint32_t kbA = (uint32_t)(lane >> 4) * 16;
    const int rowB = warp_n * 32 + (lane & 7);
    const uint32_t maskB = (uint32_t)(rowB & 7) << 4;
    const uint32_t kbB = (uint32_t)((lane >> 3) & 1) * 16;

    float acc[4][4][4] = {};

    for (int c = 0; c < NC; c++) {
        cp_wait1();
        __syncthreads();
        const uint32_t buf = sb + (uint32_t)(c & 1) * STAGE_B;
        const uint32_t aBase = buf + (uint32_t)rowA * 128;
        const uint32_t bBase = buf + 16384 + (uint32_t)rowB * 128;

#pragma unroll
        for (int k16 = 0; k16 < 4; k16++) {
            const uint32_t koffA = ((uint32_t)k16 * 32 + kbA) ^ maskA;
            const uint32_t koffB = ((uint32_t)k16 * 32 + kbB) ^ maskB;
            uint32_t ah[4][4], bh[4][2];
#pragma unroll
            for (int mi = 0; mi < 4; mi++)
                ldm_x4(ah[mi], aBase + mi * 2048 + koffA);
#pragma unroll
            for (int ni = 0; ni < 4; ni++)
                ldm_x2(bh[ni], bBase + ni * 1024 + koffB);
#pragma unroll
            for (int mi = 0; mi < 4; mi++)
#pragma unroll
                for (int ni = 0; ni < 4; ni++)
                    mma_f16(acc[mi][ni], ah[mi], bh[ni]);
        }
        __syncthreads();
        if (c + 2 < NC) load_chunk(c + 2);
        cp_commit();
    }

    // ------------------------- epilogue -------------------------
    const int rbase = m0 + warp_m * 64 + (lane >> 2);
    const int cbase = n0 + warp_n * 32 + (lane & 3) * 2;
#pragma unroll
    for (int mi = 0; mi < 4; mi++) {
#pragma unroll
        for (int half = 0; half < 2; half++) {
            const int row = rbase + mi * 16 + half * 8;
#pragma unroll
            for (int ni = 0; ni < 4; ni++) {
                const int col = cbase + ni * 8;
                float v0 = acc[mi][ni][half * 2 + 0];
                float v1 = acc[mi][ni][half * 2 + 1];
                if (bias) {
                    v0 += __ldg(&bias[col]);
                    v1 += __ldg(&bias[col + 1]);
                }
                if (GELU) {
                    float x3 = v0 * v0 * v0;
                    v0 = 0.5f * v0 * (1.0f + tanhf(0.7978845608028654f * (v0 + 0.044715f * x3)));
                    x3 = v1 * v1 * v1;
                    v1 = 0.5f * v1 * (1.0f + tanhf(0.7978845608028654f * (v1 + 0.044715f * x3)));
                }
                const size_t o = (size_t)z * cBS + (size_t)row * 512 + col;
                if (RESF) {
                    float2 q = *(const float2*)(resp + o);
                    v0 += q.x; v1 += q.y;
                }
                if (RESH) {
                    uint32_t rv = *(const uint32_t*)(resph + o);
                    __half2 rh = *reinterpret_cast<__half2*>(&rv);
                    v0 += __half2float(rh.x);
                    v1 += __half2float(rh.y);
                }
                if (WF32)
                    *(float2*)(C + o) = make_float2(v0, v1);
                if (WHALF)
                    *(uint32_t*)(Ch + o) = pack_hf2(v0, v1);
            }
        }
    }
}

// ------------------------- prep / elementwise kernels ----------------------
// Transpose + fp16: src [R, C] f32 -> dst [C, R] fp16
__global__ void k_thalf(const float* __restrict__ src, hf* __restrict__ dh,
                        int R, int C, size_t sBS, size_t dBS)
{
    __shared__ float tile[32][33];
    const int tx = threadIdx.x, ty = threadIdx.y;
    const int c0 = blockIdx.x * 32, r0 = blockIdx.y * 32;
    const int z = blockIdx.z;
    src += (size_t)z * sBS; dh += (size_t)z * dBS;
#pragma unroll
    for (int i = 0; i < 4; i++)
        tile[ty + i * 8][tx] = src[(size_t)(r0 + ty + i * 8) * C + c0 + tx];
    __syncthreads();
#pragma unroll
    for (int i = 0; i < 4; i++) {
        float v = tile[tx][ty + i * 8];
        dh[(size_t)(c0 + ty + i * 8) * R + r0 + tx] = __float2half_rn(v);
    }
}

// Fused 3-weight transpose+fp16 (W1, W2, Wout -> wh[1..3])
__global__ void k_thalf3(const float* __restrict__ s1, const float* __restrict__ s2,
                         const float* __restrict__ s3, hf* __restrict__ dh)
{
    __shared__ float tile[32][33];
    const int tx = threadIdx.x, ty = threadIdx.y;
    const int c0 = blockIdx.x * 32, r0 = blockIdx.y * 32;
    const int z = blockIdx.z;
    const float* src = (z == 0) ? s1 : (z == 1) ? s2 : s3;
    dh += (size_t)(z + 1) * 262144;
#pragma unroll
    for (int i = 0; i < 4; i++)
        tile[ty + i * 8][tx] = src[(size_t)(r0 + ty + i * 8) * 512 + c0 + tx];
    __syncthreads();
#pragma unroll
    for (int i = 0; i < 4; i++) {
        float v = tile[tx][ty + i * 8];
        dh[(size_t)(c0 + ty + i * 8) * 512 + r0 + tx] = __float2half_rn(v);
    }
}

// Fold head-mix into w_int:  W'[k*64+d, j] = sum_h alpha[h,k] * w_int[h*64+d, j]
// Output transposed fp16: dst[j*512 + i] (i = k*64+d), for GEMM B operand [n,k].
__global__ void k_fold(const float* __restrict__ alpha, const float* __restrict__ w_int,
                       hf* __restrict__ dst)
{
    __shared__ float sa[64];
    int t = threadIdx.x;
    if (t < 64) sa[t] = alpha[t];
    __syncthreads();
    int idx = blockIdx.x * 256 + t;        // < 512*512
    int j = idx & 511;                     // coalesced reads over j
    int i = idx >> 9;
    int k = i >> 6, d = i & 63;
    float s = 0.0f;
#pragma unroll
    for (int h = 0; h < 8; h++)
        s = fmaf(sa[h * 8 + k], w_int[(size_t)(h * 64 + d) * 512 + j], s);
    dst[(size_t)j * 512 + i] = __float2half_rn(s);
}

// K_rbf -> single fp16
__global__ void k_rbf_half(const float* __restrict__ pos, const float* __restrict__ sigma,
                           hf* __restrict__ kh)
{
    size_t lin = (size_t)blockIdx.x * 256 + threadIdx.x; // < 16*512*512
    int t4 = (int)(lin & 511);
    int m = (int)((lin >> 9) & 511);
    int b = (int)(lin >> 18);
    float s = __ldg(sigma);
    float inv = 1.0f / (2.0f * s * s);
    float gm = (float)m * (1.0f / 511.0f);
    float4 p = *(const float4*)(pos + (size_t)b * Nn + t4 * 4);
    float v0 = __expf(-(gm - p.x) * (gm - p.x) * inv);
    float v1 = __expf(-(gm - p.y) * (gm - p.y) * inv);
    float v2 = __expf(-(gm - p.z) * (gm - p.z) * inv);
    float v3 = __expf(-(gm - p.w) * (gm - p.w) * inv);
    size_t o = ((size_t)b * 512 + m) * 2048 + t4 * 4;
    uint2 hh;
    hh.x = pack_hf2(v0, v1); hh.y = pack_hf2(v2, v3);
    *(uint2*)(kh + o) = hh;
}

template <bool HOUT>
__global__ __launch_bounds__(256)
void k_diffuse3(const float* __restrict__ in, float* __restrict__ out,
                const float* __restrict__ coef, hf* __restrict__ oh)
{
    __shared__ float s[512 * 8];
    const int t = threadIdx.x;
    const int b = blockIdx.x >> 6;
    const int d0 = (blockIdx.x & 63) * 8;
    const int dl = t & 7;
    const size_t gbase = ((size_t)b * Mm) * Dd + d0;
    const float c = DT_C * __ldg(&coef[d0 + dl]);
#pragma unroll
    for (int i = 0; i < 16; i++) {
        int idx = t + i * 256;
        s[idx] = in[gbase + (size_t)(idx >> 3) * Dd + dl];
    }
    __syncthreads();
#pragma unroll
    for (int step = 0; step < 3; step++) {
        float nv[16];
#pragma unroll
        for (int i = 0; i < 16; i++) {
            int idx = t + i * 256;
            int m = idx >> 3;
            float v = s[idx];
            float l = (m > 0) ? s[idx - 8] : v;
            float r = (m < 511) ? s[idx + 8] : v;
            nv[i] = fmaf(c, l + r - 2.0f * v, v);
        }
        __syncthreads();
#pragma unroll
        for (int i = 0; i < 16; i++) s[t + i * 256] = nv[i];
        __syncthreads();
    }
#pragma unroll
    for (int i = 0; i < 16; i++) {
        int idx = t + i * 256;
        size_t g = gbase + (size_t)(idx >> 3) * Dd + dl;
        float v = s[idx];
        out[g] = v;
        if (HOUT) oh[g] = __float2half_rn(v);
    }
}

// sample + residual + LN1 -> fp16 (enh)
__global__ __launch_bounds__(128)
void k_sample_ln(const float* __restrict__ pos, const float* __restrict__ emb,
                 const float* __restrict__ field,
                 const float* __restrict__ gam, const float* __restrict__ bet,
                 hf* __restrict__ oh)
{
    __shared__ float ssum[4], ssq[4], sstat[2];
    int row = blockIdx.x;
    int b = row >> 11;
    float p = __ldg(&pos[row]);
    float u = fminf(fmaxf(p, 0.0f), 1.0f) * (float)(Mm - 1);
    int i0 = (int)u;
    if (i0 > Mm - 2) i0 = Mm - 2;
    float w = u - (float)i0;

    const float* f0 = field + ((size_t)b * Mm + i0) * Dd;
    int t = threadIdx.x;
    int d0 = t * 4;
    float4 a = *(const float4*)(f0 + d0);
    float4 bb = *(const float4*)(f0 + Dd + d0);
    float4 e = *(const float4*)(emb + (size_t)row * Dd + d0);
    float x[4];
    x[0] = fmaf(w, bb.x - a.x, a.x) + e.x;
    x[1] = fmaf(w, bb.y - a.y, a.y) + e.y;
    x[2] = fmaf(w, bb.z - a.z, a.z) + e.z;
    x[3] = fmaf(w, bb.w - a.w, a.w) + e.w;
    float sum = x[0] + x[1] + x[2] + x[3];
    float sq = fmaf(x[0], x[0], fmaf(x[1], x[1], fmaf(x[2], x[2], x[3] * x[3])));
#pragma unroll
    for (int o = 16; o > 0; o >>= 1) {
        sum += __shfl_down_sync(0xffffffffu, sum, o);
        sq += __shfl_down_sync(0xffffffffu, sq, o);
    }
    int wd = t >> 5, ln = t & 31;
    if (ln == 0) { ssum[wd] = sum; ssq[wd] = sq; }
    __syncthreads();
    if (t == 0) {
        float S = ssum[0] + ssum[1] + ssum[2] + ssum[3];
        float Q = ssq[0] + ssq[1] + ssq[2] + ssq[3];
        float mu = S * (1.0f / Dd);
        float var = Q * (1.0f / Dd) - mu * mu;
        sstat[0] = mu;
        sstat[1] = rsqrtf(var + 1e-5f);
    }
    __syncthreads();
    float mu = sstat[0], inv = sstat[1];
    float4 g = *(const float4*)(gam + d0);
    float4 be = *(const float4*)(bet + d0);
    float y0 = (x[0] - mu) * inv * g.x + be.x;
    float y1 = (x[1] - mu) * inv * g.y + be.y;
    float y2 = (x[2] - mu) * inv * g.z + be.z;
    float y3 = (x[3] - mu) * inv * g.w + be.w;
    size_t o = (size_t)row * Dd + d0;
    uint2 hh;
    hh.x = pack_hf2(y0, y1); hh.y = pack_hf2(y2, y3);
    *(uint2*)(oh + o) = hh;
}

// final LN2: reads fp16 pre-LN (residual already fused), writes f32 out
__global__ __launch_bounds__(128)
void k_ln2(const hf* __restrict__ pre, const float* __restrict__ gam,
           const float* __restrict__ bet, float* __restrict__ out)
{
    __shared__ float ssum[4], ssq[4], sstat[2];
    int row = blockIdx.x;
    int t = threadIdx.x;
    int d0 = t * 4;
    size_t o = (size_t)row * Dd + d0;
    uint2 hv = *(const uint2*)(pre + o);
    __half2 h01 = *reinterpret_cast<__half2*>(&hv.x);
    __half2 h23 = *reinterpret_cast<__half2*>(&hv.y);
    float x[4] = {__half2float(h01.x), __half2float(h01.y),
                  __half2float(h23.x), __half2float(h23.y)};
    float sum = x[0] + x[1] + x[2] + x[3];
    float sq = fmaf(x[0], x[0], fmaf(x[1], x[1], fmaf(x[2], x[2], x[3] * x[3])));
#pragma unroll
    for (int s = 16; s > 0; s >>= 1) {
        sum += __shfl_down_sync(0xffffffffu, sum, s);
        sq += __shfl_down_sync(0xffffffffu, sq, s);
    }
    int wd = t >> 5, ln = t & 31;
    if (ln == 0) { ssum[wd] = sum; ssq[wd] = sq; }
    __syncthreads();
    if (t == 0) {
        float S = ssum[0] + ssum[1] + ssum[2] + ssum[3];
        float Q = ssq[0] + ssq[1] + ssq[2] + ssq[3];
        float mu = S * (1.0f / Dd);
        float var = Q * (1.0f / Dd) - mu * mu;
        sstat[0] = mu;
        sstat[1] = rsqrtf(var + 1e-5f);
    }
    __syncthreads();
    float mu = sstat[0], inv = sstat[1];
    float4 g = *(const float4*)(gam + d0);
    float4 be = *(const float4*)(bet + d0);
    *(float4*)(out + o) = make_float4(
        (x[0] - mu) * inv * g.x + be.x, (x[1] - mu) * inv * g.y + be.y,
        (x[2] - mu) * inv * g.z + be.z, (x[3] - mu) * inv * g.w + be.w);
}

// ---------------------------------------------------------------------------
extern "C" void kernel_launch(void* const* d_in, const int* in_sizes, int n_in,
                              void* d_out, int out_size)
{
    const float* emb   = (const float*)d_in[0];
    const float* pos   = (const float*)d_in[1];
    const float* sigma = (const float*)d_in[2];
    const float* alpha = (const float*)d_in[3];
    const float* w_int = (const float*)d_in[4];
    const float* b_int = (const float*)d_in[5];
    const float* dcoef = (const float*)d_in[6];
    const float* W1    = (const float*)d_in[7];
    const float* b1    = (const float*)d_in[8];
    const float* W2    = (const float*)d_in[9];
    const float* b2    = (const float*)d_in[10];
    const float* ecoef = (const float*)d_in[11];
    const float* ln1g  = (const float*)d_in[12];
    const float* ln1b  = (const float*)d_in[13];
    const float* Wout  = (const float*)d_in[14];
    const float* bout  = (const float*)d_in[15];
    const float* ln2g  = (const float*)d_in[16];
    const float* ln2b  = (const float*)d_in[17];
    float* out = (float*)d_out;

    hf *h1, *h2, *ebh, *wh;
    float *field, *tmp2;
    cudaGetSymbolAddress((void**)&h1, g_h1);
    cudaGetSymbolAddress((void**)&h2, g_h2);
    cudaGetSymbolAddress((void**)&ebh, g_ebh);
    cudaGetSymbolAddress((void**)&wh, g_wh);
    cudaGetSymbolAddress((void**)&field, g_field);
    cudaGetSymbolAddress((void**)&tmp2, g_tmp2);

    cudaFuncSetAttribute(k_gemm_mma<false, false, false, true, true>,
                         cudaFuncAttributeMaxDynamicSharedMemorySize, SMEM_SZ);
    cudaFuncSetAttribute(k_gemm_mma<false, true, false, true, false>,
                         cudaFuncAttributeMaxDynamicSharedMemorySize, SMEM_SZ);
    cudaFuncSetAttribute(k_gemm_mma<true, false, false, false, true>,
                         cudaFuncAttributeMaxDynamicSharedMemorySize, SMEM_SZ);
    cudaFuncSetAttribute(k_gemm_mma<false, false, true, false, true>,
                         cudaFuncAttributeMaxDynamicSharedMemorySize, SMEM_SZ);

    dim3 tT(32, 8);

    // folded head-mix weight: wh[0] = (alpha-fold of w_int)^T
    k_fold<<<1024, 256>>>(alpha, w_int, wh);

    // W1, W2, Wout^T fp16 -> wh[1..3]
    k_thalf3<<<dim3(16, 16, 3), tT>>>(W1, W2, Wout, wh);

    // embT fp16  [b, d, t]
    k_thalf<<<dim3(16, 64, 16), tT>>>(emb, ebh, Nn, Dd,
                                      (size_t)Nn * Dd, (size_t)Dd * Nn);

    // K-RBF fp16 into h1 (flat 16x512x2048)
    k_rbf_half<<<16384, 256>>>(pos, sigma, h1);

    // 1) field = K @ emb^T'  (f32 -> field, fp16 -> h2)   [batched, Kdim=2048]
    k_gemm_mma<false, false, false, true, true><<<dim3(4, 4, 16), 256, SMEM_SZ>>>(
        h1, 2048, (size_t)512 * 2048,
        ebh, 2048, (size_t)512 * 2048,
        nullptr, nullptr, nullptr, field, h2, (size_t)512 * 512, 2048);

    // 2) tmp2 = field + field @ W' + b_int   (head-mix folded into W')
    k_gemm_mma<false, true, false, true, false><<<dim3(64, 4, 1), 256, SMEM_SZ>>>(
        h2, 512, 0, wh + 0 * 262144, 512, 0,
        b_int, field, nullptr, tmp2, nullptr, 0, 512);

    // 3) diffusion x3 -> field (+ fp16 h2)
    k_diffuse3<true><<<Bn * 64, 256>>>(tmp2, field, dcoef, h2);

    // 4) gelu(field @ W1 + b1) -> h1 (fp16)
    k_gemm_mma<true, false, false, false, true><<<dim3(64, 4, 1), 256, SMEM_SZ>>>(
        h2, 512, 0, wh + 1 * 262144, 512, 0,
        b1, nullptr, nullptr, nullptr, h1, 0, 512);

    // 5) tmp2 = field + gelu @ W2 + b2
    k_gemm_mma<false, true, false, true, false><<<dim3(64, 4, 1), 256, SMEM_SZ>>>(
        h1, 512, 0, wh + 2 * 262144, 512, 0,
        b2, field, nullptr, tmp2, nullptr, 0, 512);

    // 6) diffusion x3 -> field
    k_diffuse3<false><<<Bn * 64, 256>>>(tmp2, field, ecoef, nullptr);

    // 7) enh = LN1(sample(field) + emb) -> h1 (fp16)
    k_sample_ln<<<Bn * Nn, 128>>>(pos, emb, field, ln1g, ln1b, h1);

    // 8) preLN2 = enh @ Wout + bout + enh -> ebh (fp16, residual fused)
    k_gemm_mma<false, false, true, false, true><<<dim3(256, 4, 1), 256, SMEM_SZ>>>(
        h1, 512, 0, wh + 3 * 262144, 512, 0,
        bout, nullptr, h1, nullptr, ebh, 0, 512);

    // 9) out = LN2(preLN2)
    k_ln2<<<Bn * Nn, 128>>>(ebh, ln2g, ln2b, out);
}

// round 12
// speedup vs baseline: 1.0559x; 1.0262x over previous
#include <cuda_runtime.h>
#include <cuda_fp16.h>
#include <math.h>
#include <stdint.h>

#define Bn 16
#define Nn 2048
#define Dd 512
#define Mm 512
#define DT_C 0.01f

typedef __half hf;

// ------------------------- device scratch (no runtime alloc) ---------------
__device__ hf g_h1[(size_t)32768 * 512];   // 32MB  (K-RBF -> gelu -> enh)
__device__ hf g_h2[(size_t)8192 * 512];    // 8MB   (field fp16)
__device__ hf g_ebh[(size_t)Bn * Dd * Nn]; // 32MB  embT [b,d,t]; later pre-LN2 fp16
__device__ hf g_wh[4][512 * 512];          // 2MB   [0]=folded W', [1..3]=W1,W2,Wout^T
__device__ float g_field[(size_t)Bn * Mm * Dd]; // 16MB
__device__ float g_tmp2[(size_t)Bn * Mm * Dd];  // 16MB

// ------------------------- helpers -----------------------------------------
__device__ __forceinline__ uint32_t smem_u32(const void* p) {
    uint32_t a;
    asm("{ .reg .u64 t; cvta.to.shared.u64 t, %1; cvt.u32.u64 %0, t; }" : "=r"(a) : "l"(p));
    return a;
}
__device__ __forceinline__ uint32_t pack_hf2(float a, float b) {
    __half2 t = __floats2half2_rn(a, b);
    return *reinterpret_cast<uint32_t*>(&t);
}
__device__ __forceinline__ void cp16(uint32_t dst, const void* src) {
    asm volatile("cp.async.cg.shared.global [%0], [%1], 16;" :: "r"(dst), "l"(src));
}
__device__ __forceinline__ void cp_commit() {
    asm volatile("cp.async.commit_group;");
}
__device__ __forceinline__ void cp_wait1() {
    asm volatile("cp.async.wait_group 1;");
}
__device__ __forceinline__ void ldm_x4(uint32_t* r, uint32_t a) {
    asm volatile("ldmatrix.sync.aligned.m8n8.x4.shared.b16 {%0,%1,%2,%3}, [%4];"
                 : "=r"(r[0]), "=r"(r[1]), "=r"(r[2]), "=r"(r[3]) : "r"(a));
}
__device__ __forceinline__ void mma_f16(float* c, const uint32_t* a, const uint32_t* b) {
    asm volatile(
        "mma.sync.aligned.m16n8k16.row.col.f32.f16.f16.f32 "
        "{%0,%1,%2,%3}, {%4,%5,%6,%7}, {%8,%9}, {%0,%1,%2,%3};"
        : "+f"(c[0]), "+f"(c[1]), "+f"(c[2]), "+f"(c[3])
        : "r"(a[0]), "r"(a[1]), "r"(a[2]), "r"(a[3]), "r"(b[0]), "r"(b[1]));
}

// ------------------------- HMMA GEMM (fp16, single-pass, 2-stage) -----------
// D[128,128] CTA tile; 8 warps 2(M)x4(N), warp tile 64x32.
// A, B single fp16 K-major. SMEM/stage: A 16K | B 16K = 32KB; 2 stages = 64KB
// -> 2 CTAs/SM. B fragments loaded pairwise with ldmatrix.x4.
#define STAGE_B 32768u
#define SMEM_SZ (2 * 32768)

template <bool GELU, bool RESF, bool RESH, bool WF32, bool WHALF>
__global__ __launch_bounds__(256, 2)
void k_gemm_mma(const hf* __restrict__ A, size_t aRS, size_t aBS,
                const hf* __restrict__ B, size_t bRS, size_t bBS,
                const float* __restrict__ bias, const float* __restrict__ resp,
                const hf* __restrict__ resph,
                float* __restrict__ C, hf* __restrict__ Ch,
                size_t cBS, int Kdim)
{
    extern __shared__ char smem[];
    const uint32_t sb = smem_u32(smem);
    const int t = threadIdx.x;
    const int wid = t >> 5;
    const int lane = t & 31;
    const int warp_m = wid & 1;   // 2 warps over M (64 rows each)
    const int warp_n = wid >> 1;  // 4 warps over N (32 cols each)

    const int m0 = blockIdx.x * 128;
    const int n0 = blockIdx.y * 128;
    const int z = blockIdx.z;

    const hf* pA = A + (size_t)z * aBS;
    const hf* pB = B + (size_t)z * bBS;

    const int NC = Kdim >> 6;

    auto load_chunk = [&](int c) {
        const uint32_t buf = sb + (uint32_t)(c & 1) * STAGE_B;
        const int k0 = c << 6;
#pragma unroll
        for (int i = 0; i < 4; i++) {
            int id = t + i * 256;
            int row = id >> 3;
            int seg = id & 7;
            uint32_t soff = (uint32_t)row * 128 + (uint32_t)((seg * 16) ^ ((row & 7) << 4));
            cp16(buf + soff,         pA + (size_t)(m0 + row) * aRS + k0 + seg * 8);
            cp16(buf + 16384 + soff, pB + (size_t)(n0 + row) * bRS + k0 + seg * 8);
        }
    };

    load_chunk(0); cp_commit();
    if (NC > 1) { load_chunk(1); cp_commit(); }

    // fragment address precomputation
    const int rowA = warp_m * 64 + (lane & 15);
    const uint32_t maskA = (uint32_t)(rowA & 7) << 4;
    const uint32_t kbA = (uint32_t)(lane >> 4) * 16;
    // B x4: lanes 0-7 rows n..n+7 (k0), 8-15 same rows (k8), 16-23 rows n+8..n+15 (k0),
    // 24-31 rows n+8.. (k8). Mask depends only on lane&7 (rows differ by 8).
    const int rowB = warp_n * 32 + ((lane >> 4) & 1) * 8 + (lane & 7);
    const uint32_t maskB = (uint32_t)(lane & 7) << 4;
    const uint32_t kbB = (uint32_t)((lane >> 3) & 1) * 16;

    float acc[4][4][4] = {};

    for (int c = 0; c < NC; c++) {
        cp_wait1();
        __syncthreads();
        const uint32_t buf = sb + (uint32_t)(c & 1) * STAGE_B;
        const uint32_t aBase = buf + (uint32_t)rowA * 128;
        const uint32_t bBase = buf + 16384 + (uint32_t)rowB * 128;

#pragma unroll
        for (int k16 = 0; k16 < 4; k16++) {
            const uint32_t koffA = ((uint32_t)k16 * 32 + kbA) ^ maskA;
            const uint32_t koffB = ((uint32_t)k16 * 32 + kbB) ^ maskB;
            uint32_t ah[4][4], bh[4][2];
#pragma unroll
            for (int mi = 0; mi < 4; mi++)
                ldm_x4(ah[mi], aBase + mi * 2048 + koffA);
#pragma unroll
            for (int n4 = 0; n4 < 2; n4++) {
                uint32_t br[4];
                ldm_x4(br, bBase + n4 * 2048 + koffB);
                bh[n4 * 2 + 0][0] = br[0]; bh[n4 * 2 + 0][1] = br[1];
                bh[n4 * 2 + 1][0] = br[2]; bh[n4 * 2 + 1][1] = br[3];
            }
#pragma unroll
            for (int mi = 0; mi < 4; mi++)
#pragma unroll
                for (int ni = 0; ni < 4; ni++)
                    mma_f16(acc[mi][ni], ah[mi], bh[ni]);
        }
        __syncthreads();
        if (c + 2 < NC) load_chunk(c + 2);
        cp_commit();
    }

    // ------------------------- epilogue -------------------------
    const int rbase = m0 + warp_m * 64 + (lane >> 2);
    const int cbase = n0 + warp_n * 32 + (lane & 3) * 2;
#pragma unroll
    for (int mi = 0; mi < 4; mi++) {
#pragma unroll
        for (int half = 0; half < 2; half++) {
            const int row = rbase + mi * 16 + half * 8;
#pragma unroll
            for (int ni = 0; ni < 4; ni++) {
                const int col = cbase + ni * 8;
                float v0 = acc[mi][ni][half * 2 + 0];
                float v1 = acc[mi][ni][half * 2 + 1];
                if (bias) {
                    v0 += __ldg(&bias[col]);
                    v1 += __ldg(&bias[col + 1]);
                }
                if (GELU) {
                    float x3 = v0 * v0 * v0;
                    v0 = 0.5f * v0 * (1.0f + tanhf(0.7978845608028654f * (v0 + 0.044715f * x3)));
                    x3 = v1 * v1 * v1;
                    v1 = 0.5f * v1 * (1.0f + tanhf(0.7978845608028654f * (v1 + 0.044715f * x3)));
                }
                const size_t o = (size_t)z * cBS + (size_t)row * 512 + col;
                if (RESF) {
                    float2 q = *(const float2*)(resp + o);
                    v0 += q.x; v1 += q.y;
                }
                if (RESH) {
                    uint32_t rv = *(const uint32_t*)(resph + o);
                    __half2 rh = *reinterpret_cast<__half2*>(&rv);
                    v0 += __half2float(rh.x);
                    v1 += __half2float(rh.y);
                }
                if (WF32)
                    *(float2*)(C + o) = make_float2(v0, v1);
                if (WHALF)
                    *(uint32_t*)(Ch + o) = pack_hf2(v0, v1);
            }
        }
    }
}

// ------------------------- prep / elementwise kernels ----------------------
// Transpose + fp16: src [R, C] f32 -> dst [C, R] fp16
__global__ void k_thalf(const float* __restrict__ src, hf* __restrict__ dh,
                        int R, int C, size_t sBS, size_t dBS)
{
    __shared__ float tile[32][33];
    const int tx = threadIdx.x, ty = threadIdx.y;
    const int c0 = blockIdx.x * 32, r0 = blockIdx.y * 32;
    const int z = blockIdx.z;
    src += (size_t)z * sBS; dh += (size_t)z * dBS;
#pragma unroll
    for (int i = 0; i < 4; i++)
        tile[ty + i * 8][tx] = src[(size_t)(r0 + ty + i * 8) * C + c0 + tx];
    __syncthreads();
#pragma unroll
    for (int i = 0; i < 4; i++) {
        float v = tile[tx][ty + i * 8];
        dh[(size_t)(c0 + ty + i * 8) * R + r0 + tx] = __float2half_rn(v);
    }
}

// Fused weight prep (one launch): z<3: transpose W1/W2/Wout -> wh[z+1];
// z==3: fold head-mix into w_int -> wh[0] (transposed).
__global__ void k_wprep(const float* __restrict__ w_int, const float* __restrict__ alpha,
                        const float* __restrict__ s1, const float* __restrict__ s2,
                        const float* __restrict__ s3, hf* __restrict__ dh)
{
    const int t = threadIdx.x;
    const int z = blockIdx.z;
    if (z < 3) {
        __shared__ float tile[32][33];
        const int tx = t & 31, ty = t >> 5;
        const int c0 = blockIdx.x * 32, r0 = blockIdx.y * 32;
        const float* src = (z == 0) ? s1 : (z == 1) ? s2 : s3;
        hf* dst = dh + (size_t)(z + 1) * 262144;
#pragma unroll
        for (int i = 0; i < 4; i++)
            tile[ty + i * 8][tx] = src[(size_t)(r0 + ty + i * 8) * 512 + c0 + tx];
        __syncthreads();
#pragma unroll
        for (int i = 0; i < 4; i++) {
            float v = tile[tx][ty + i * 8];
            dst[(size_t)(c0 + ty + i * 8) * 512 + r0 + tx] = __float2half_rn(v);
        }
    } else {
        __shared__ float sa[64];
        if (t < 64) sa[t] = alpha[t];
        __syncthreads();
        const int blk = blockIdx.y * 16 + blockIdx.x; // 0..255
#pragma unroll
        for (int it = 0; it < 4; it++) {
            int idx = blk * 1024 + it * 256 + t;   // < 512*512
            int j = idx & 511;
            int i = idx >> 9;
            int k = i >> 6, d = i & 63;
            float s = 0.0f;
#pragma unroll
            for (int h = 0; h < 8; h++)
                s = fmaf(sa[h * 8 + k], w_int[(size_t)(h * 64 + d) * 512 + j], s);
            dh[(size_t)j * 512 + i] = __float2half_rn(s);
        }
    }
}

// K_rbf -> fp16, 8 elements (one 16B store pair) per thread
__global__ void k_rbf_half(const float* __restrict__ pos, const float* __restrict__ sigma,
                           hf* __restrict__ kh)
{
    size_t lin = (size_t)blockIdx.x * 256 + threadIdx.x; // < 16*512*256
    int t8 = (int)(lin & 255);
    int m = (int)((lin >> 8) & 511);
    int b = (int)(lin >> 17);
    float s = __ldg(sigma);
    float inv = 1.0f / (2.0f * s * s);
    float gm = (float)m * (1.0f / 511.0f);
    const float* pp = pos + (size_t)b * Nn + t8 * 8;
    float4 p0 = *(const float4*)pp;
    float4 p1 = *(const float4*)(pp + 4);
    float d0 = gm - p0.x, d1 = gm - p0.y, d2 = gm - p0.z, d3 = gm - p0.w;
    float d4 = gm - p1.x, d5 = gm - p1.y, d6 = gm - p1.z, d7 = gm - p1.w;
    uint4 o4;
    o4.x = pack_hf2(__expf(-d0 * d0 * inv), __expf(-d1 * d1 * inv));
    o4.y = pack_hf2(__expf(-d2 * d2 * inv), __expf(-d3 * d3 * inv));
    o4.z = pack_hf2(__expf(-d4 * d4 * inv), __expf(-d5 * d5 * inv));
    o4.w = pack_hf2(__expf(-d6 * d6 * inv), __expf(-d7 * d7 * inv));
    *(uint4*)(kh + ((size_t)b * 512 + m) * 2048 + t8 * 8) = o4;
}

template <bool HOUT>
__global__ __launch_bounds__(256)
void k_diffuse3(const float* __restrict__ in, float* __restrict__ out,
                const float* __restrict__ coef, hf* __restrict__ oh)
{
    __shared__ float s[512 * 8];
    const int t = threadIdx.x;
    const int b = blockIdx.x >> 6;
    const int d0 = (blockIdx.x & 63) * 8;
    const int dl = t & 7;
    const size_t gbase = ((size_t)b * Mm) * Dd + d0;
    const float c = DT_C * __ldg(&coef[d0 + dl]);
#pragma unroll
    for (int i = 0; i < 16; i++) {
        int idx = t + i * 256;
        s[idx] = in[gbase + (size_t)(idx >> 3) * Dd + dl];
    }
    __syncthreads();
#pragma unroll
    for (int step = 0; step < 3; step++) {
        float nv[16];
#pragma unroll
        for (int i = 0; i < 16; i++) {
            int idx = t + i * 256;
            int m = idx >> 3;
            float v = s[idx];
            float l = (m > 0) ? s[idx - 8] : v;
            float r = (m < 511) ? s[idx + 8] : v;
            nv[i] = fmaf(c, l + r - 2.0f * v, v);
        }
        __syncthreads();
#pragma unroll
        for (int i = 0; i < 16; i++) s[t + i * 256] = nv[i];
        __syncthreads();
    }
#pragma unroll
    for (int i = 0; i < 16; i++) {
        int idx = t + i * 256;
        size_t g = gbase + (size_t)(idx >> 3) * Dd + dl;
        float v = s[idx];
        out[g] = v;
        if (HOUT) oh[g] = __float2half_rn(v);
    }
}

// sample + residual + LN1 -> fp16 (enh)
__global__ __launch_bounds__(128)
void k_sample_ln(const float* __restrict__ pos, const float* __restrict__ emb,
                 const float* __restrict__ field,
                 const float* __restrict__ gam, const float* __restrict__ bet,
                 hf* __restrict__ oh)
{
    __shared__ float ssum[4], ssq[4], sstat[2];
    int row = blockIdx.x;
    int b = row >> 11;
    float p = __ldg(&pos[row]);
    float u = fminf(fmaxf(p, 0.0f), 1.0f) * (float)(Mm - 1);
    int i0 = (int)u;
    if (i0 > Mm - 2) i0 = Mm - 2;
    float w = u - (float)i0;

    const float* f0 = field + ((size_t)b * Mm + i0) * Dd;
    int t = threadIdx.x;
    int d0 = t * 4;
    float4 a = *(const float4*)(f0 + d0);
    float4 bb = *(const float4*)(f0 + Dd + d0);
    float4 e = *(const float4*)(emb + (size_t)row * Dd + d0);
    float x[4];
    x[0] = fmaf(w, bb.x - a.x, a.x) + e.x;
    x[1] = fmaf(w, bb.y - a.y, a.y) + e.y;
    x[2] = fmaf(w, bb.z - a.z, a.z) + e.z;
    x[3] = fmaf(w, bb.w - a.w, a.w) + e.w;
    float sum = x[0] + x[1] + x[2] + x[3];
    float sq = fmaf(x[0], x[0], fmaf(x[1], x[1], fmaf(x[2], x[2], x[3] * x[3])));
#pragma unroll
    for (int o = 16; o > 0; o >>= 1) {
        sum += __shfl_down_sync(0xffffffffu, sum, o);
        sq += __shfl_down_sync(0xffffffffu, sq, o);
    }
    int wd = t >> 5, ln = t & 31;
    if (ln == 0) { ssum[wd] = sum; ssq[wd] = sq; }
    __syncthreads();
    if (t == 0) {
        float S = ssum[0] + ssum[1] + ssum[2] + ssum[3];
        float Q = ssq[0] + ssq[1] + ssq[2] + ssq[3];
        float mu = S * (1.0f / Dd);
        float var = Q * (1.0f / Dd) - mu * mu;
        sstat[0] = mu;
        sstat[1] = rsqrtf(var + 1e-5f);
    }
    __syncthreads();
    float mu = sstat[0], inv = sstat[1];
    float4 g = *(const float4*)(gam + d0);
    float4 be = *(const float4*)(bet + d0);
    float y0 = (x[0] - mu) * inv * g.x + be.x;
    float y1 = (x[1] - mu) * inv * g.y + be.y;
    float y2 = (x[2] - mu) * inv * g.z + be.z;
    float y3 = (x[3] - mu) * inv * g.w + be.w;
    size_t o = (size_t)row * Dd + d0;
    uint2 hh;
    hh.x = pack_hf2(y0, y1); hh.y = pack_hf2(y2, y3);
    *(uint2*)(oh + o) = hh;
}

// final LN2: reads fp16 pre-LN (residual already fused), writes f32 out
__global__ __launch_bounds__(128)
void k_ln2(const hf* __restrict__ pre, const float* __restrict__ gam,
           const float* __restrict__ bet, float* __restrict__ out)
{
    __shared__ float ssum[4], ssq[4], sstat[2];
    int row = blockIdx.x;
    int t = threadIdx.x;
    int d0 = t * 4;
    size_t o = (size_t)row * Dd + d0;
    uint2 hv = *(const uint2*)(pre + o);
    __half2 h01 = *reinterpret_cast<__half2*>(&hv.x);
    __half2 h23 = *reinterpret_cast<__half2*>(&hv.y);
    float x[4] = {__half2float(h01.x), __half2float(h01.y),
                  __half2float(h23.x), __half2float(h23.y)};
    float sum = x[0] + x[1] + x[2] + x[3];
    float sq = fmaf(x[0], x[0], fmaf(x[1], x[1], fmaf(x[2], x[2], x[3] * x[3])));
#pragma unroll
    for (int s = 16; s > 0; s >>= 1) {
        sum += __shfl_down_sync(0xffffffffu, sum, s);
        sq += __shfl_down_sync(0xffffffffu, sq, s);
    }
    int wd = t >> 5, ln = t & 31;
    if (ln == 0) { ssum[wd] = sum; ssq[wd] = sq; }
    __syncthreads();
    if (t == 0) {
        float S = ssum[0] + ssum[1] + ssum[2] + ssum[3];
        float Q = ssq[0] + ssq[1] + ssq[2] + ssq[3];
        float mu = S * (1.0f / Dd);
        float var = Q * (1.0f / Dd) - mu * mu;
        sstat[0] = mu;
        sstat[1] = rsqrtf(var + 1e-5f);
    }
    __syncthreads();
    float mu = sstat[0], inv = sstat[1];
    float4 g = *(const float4*)(gam + d0);
    float4 be = *(const float4*)(bet + d0);
    *(float4*)(out + o) = make_float4(
        (x[0] - mu) * inv * g.x + be.x, (x[1] - mu) * inv * g.y + be.y,
        (x[2] - mu) * inv * g.z + be.z, (x[3] - mu) * inv * g.w + be.w);
}

// ---------------------------------------------------------------------------
extern "C" void kernel_launch(void* const* d_in, const int* in_sizes, int n_in,
                              void* d_out, int out_size)
{
    const float* emb   = (const float*)d_in[0];
    const float* pos   = (const float*)d_in[1];
    const float* sigma = (const float*)d_in[2];
    const float* alpha = (const float*)d_in[3];
    const float* w_int = (const float*)d_in[4];
    const float* b_int = (const float*)d_in[5];
    const float* dcoef = (const float*)d_in[6];
    const float* W1    = (const float*)d_in[7];
    const float* b1    = (const float*)d_in[8];
    const float* W2    = (const float*)d_in[9];
    const float* b2    = (const float*)d_in[10];
    const float* ecoef = (const float*)d_in[11];
    const float* ln1g  = (const float*)d_in[12];
    const float* ln1b  = (const float*)d_in[13];
    const float* Wout  = (const float*)d_in[14];
    const float* bout  = (const float*)d_in[15];
    const float* ln2g  = (const float*)d_in[16];
    const float* ln2b  = (const float*)d_in[17];
    float* out = (float*)d_out;

    hf *h1, *h2, *ebh, *wh;
    float *field, *tmp2;
    cudaGetSymbolAddress((void**)&h1, g_h1);
    cudaGetSymbolAddress((void**)&h2, g_h2);
    cudaGetSymbolAddress((void**)&ebh, g_ebh);
    cudaGetSymbolAddress((void**)&wh, g_wh);
    cudaGetSymbolAddress((void**)&field, g_field);
    cudaGetSymbolAddress((void**)&tmp2, g_tmp2);

    cudaFuncSetAttribute(k_gemm_mma<false, false, false, true, true>,
                         cudaFuncAttributeMaxDynamicSharedMemorySize, SMEM_SZ);
    cudaFuncSetAttribute(k_gemm_mma<false, true, false, true, false>,
                         cudaFuncAttributeMaxDynamicSharedMemorySize, SMEM_SZ);
    cudaFuncSetAttribute(k_gemm_mma<true, false, false, false, true>,
                         cudaFuncAttributeMaxDynamicSharedMemorySize, SMEM_SZ);
    cudaFuncSetAttribute(k_gemm_mma<false, false, true, false, true>,
                         cudaFuncAttributeMaxDynamicSharedMemorySize, SMEM_SZ);

    dim3 tT(32, 8);

    // weight prep: wh[0]=folded W', wh[1..3]=W1,W2,Wout^T (single launch)
    k_wprep<<<dim3(16, 16, 4), 256>>>(w_int, alpha, W1, W2, Wout, wh);

    // embT fp16  [b, d, t]
    k_thalf<<<dim3(16, 64, 16), tT>>>(emb, ebh, Nn, Dd,
                                      (size_t)Nn * Dd, (size_t)Dd * Nn);

    // K-RBF fp16 into h1 (flat 16x512x2048), 8 elems/thread
    k_rbf_half<<<8192, 256>>>(pos, sigma, h1);

    // 1) field = K @ emb^T'  (f32 -> field, fp16 -> h2)   [batched, Kdim=2048]
    k_gemm_mma<false, false, false, true, true><<<dim3(4, 4, 16), 256, SMEM_SZ>>>(
        h1, 2048, (size_t)512 * 2048,
        ebh, 2048, (size_t)512 * 2048,
        nullptr, nullptr, nullptr, field, h2, (size_t)512 * 512, 2048);

    // 2) tmp2 = field + field @ W' + b_int   (head-mix folded into W')
    k_gemm_mma<false, true, false, true, false><<<dim3(64, 4, 1), 256, SMEM_SZ>>>(
        h2, 512, 0, wh + 0 * 262144, 512, 0,
        b_int, field, nullptr, tmp2, nullptr, 0, 512);

    // 3) diffusion x3 -> field (+ fp16 h2)
    k_diffuse3<true><<<Bn * 64, 256>>>(tmp2, field, dcoef, h2);

    // 4) gelu(field @ W1 + b1) -> h1 (fp16)
    k_gemm_mma<true, false, false, false, true><<<dim3(64, 4, 1), 256, SMEM_SZ>>>(
        h2, 512, 0, wh + 1 * 262144, 512, 0,
        b1, nullptr, nullptr, nullptr, h1, 0, 512);

    // 5) tmp2 = field + gelu @ W2 + b2
    k_gemm_mma<false, true, false, true, false><<<dim3(64, 4, 1), 256, SMEM_SZ>>>(
        h1, 512, 0, wh + 2 * 262144, 512, 0,
        b2, field, nullptr, tmp2, nullptr, 0, 512);

    // 6) diffusion x3 -> field
    k_diffuse3<false><<<Bn * 64, 256>>>(tmp2, field, ecoef, nullptr);

    // 7) enh = LN1(sample(field) + emb) -> h1 (fp16)
    k_sample_ln<<<Bn * Nn, 128>>>(pos, emb, field, ln1g, ln1b, h1);

    // 8) preLN2 = enh @ Wout + bout + enh -> ebh (fp16, residual fused)
    k_gemm_mma<false, false, true, false, true><<<dim3(256, 4, 1), 256, SMEM_SZ>>>(
        h1, 512, 0, wh + 3 * 262144, 512, 0,
        bout, nullptr, h1, nullptr, ebh, 0, 512);

    // 9) out = LN2(preLN2)
    k_ln2<<<Bn * Nn, 128>>>(ebh, ln2g, ln2b, out);
}

// round 13
// speedup vs baseline: 1.1076x; 1.0490x over previous
#include <cuda_runtime.h>
#include <cuda_fp16.h>
#include <math.h>
#include <stdint.h>

#define Bn 16
#define Nn 2048
#define Dd 512
#define Mm 512
#define DT_C 0.01f

typedef __half hf;

// ------------------------- device scratch (no runtime alloc) ---------------
__device__ hf g_h1[(size_t)32768 * 512];   // 32MB  (K-RBF A / gelu / enh)
__device__ hf g_h2[(size_t)8192 * 512];    // 8MB   (field fp16)
__device__ hf g_ebh[(size_t)Bn * Dd * Nn]; // 32MB  embT [b,d,t]; later pre-LN2 fp16
__device__ hf g_wh[4][512 * 512];          // 2MB   [0]=W' fold, [1]=W1^T, [2]=W2^T, [3]=(Wout+I)^T
__device__ float g_field[(size_t)Bn * Mm * Dd]; // 16MB
__device__ float g_tmp2[(size_t)Bn * Mm * Dd];  // 16MB

// ------------------------- helpers -----------------------------------------
__device__ __forceinline__ uint32_t smem_u32(const void* p) {
    uint32_t a;
    asm("{ .reg .u64 t; cvta.to.shared.u64 t, %1; cvt.u32.u64 %0, t; }" : "=r"(a) : "l"(p));
    return a;
}
__device__ __forceinline__ uint32_t pack_hf2(float a, float b) {
    __half2 t = __floats2half2_rn(a, b);
    return *reinterpret_cast<uint32_t*>(&t);
}
__device__ __forceinline__ void cp16(uint32_t dst, const void* src) {
    asm volatile("cp.async.cg.shared.global [%0], [%1], 16;" :: "r"(dst), "l"(src));
}
__device__ __forceinline__ void cp_commit() {
    asm volatile("cp.async.commit_group;");
}
__device__ __forceinline__ void cp_wait1() {
    asm volatile("cp.async.wait_group 1;");
}
__device__ __forceinline__ void ldm_x4(uint32_t* r, uint32_t a) {
    asm volatile("ldmatrix.sync.aligned.m8n8.x4.shared.b16 {%0,%1,%2,%3}, [%4];"
                 : "=r"(r[0]), "=r"(r[1]), "=r"(r[2]), "=r"(r[3]) : "r"(a));
}
__device__ __forceinline__ void mma_f16(float* c, const uint32_t* a, const uint32_t* b) {
    asm volatile(
        "mma.sync.aligned.m16n8k16.row.col.f32.f16.f16.f32 "
        "{%0,%1,%2,%3}, {%4,%5,%6,%7}, {%8,%9}, {%0,%1,%2,%3};"
        : "+f"(c[0]), "+f"(c[1]), "+f"(c[2]), "+f"(c[3])
        : "r"(a[0]), "r"(a[1]), "r"(a[2]), "r"(a[3]), "r"(b[0]), "r"(b[1]));
}

// ------------------------- HMMA GEMM (fp16, single-pass, 2-stage) -----------
#define STAGE_B 32768u
#define SMEM_SZ (2 * 32768)

template <bool GELU, bool RESF, bool RESH, bool WF32, bool WHALF>
__global__ __launch_bounds__(256, 2)
void k_gemm_mma(const hf* __restrict__ A, size_t aRS, size_t aBS,
                const hf* __restrict__ B, size_t bRS, size_t bBS,
                const float* __restrict__ bias, const float* __restrict__ resp,
                const hf* __restrict__ resph,
                float* __restrict__ C, hf* __restrict__ Ch,
                size_t cBS, int Kdim)
{
    extern __shared__ char smem[];
    const uint32_t sb = smem_u32(smem);
    const int t = threadIdx.x;
    const int wid = t >> 5;
    const int lane = t & 31;
    const int warp_m = wid & 1;
    const int warp_n = wid >> 1;

    const int m0 = blockIdx.x * 128;
    const int n0 = blockIdx.y * 128;
    const int z = blockIdx.z;

    const hf* pA = A + (size_t)z * aBS;
    const hf* pB = B + (size_t)z * bBS;

    const int NC = Kdim >> 6;

    auto load_chunk = [&](int c) {
        const uint32_t buf = sb + (uint32_t)(c & 1) * STAGE_B;
        const int k0 = c << 6;
#pragma unroll
        for (int i = 0; i < 4; i++) {
            int id = t + i * 256;
            int row = id >> 3;
            int seg = id & 7;
            uint32_t soff = (uint32_t)row * 128 + (uint32_t)((seg * 16) ^ ((row & 7) << 4));
            cp16(buf + soff,         pA + (size_t)(m0 + row) * aRS + k0 + seg * 8);
            cp16(buf + 16384 + soff, pB + (size_t)(n0 + row) * bRS + k0 + seg * 8);
        }
    };

    load_chunk(0); cp_commit();
    if (NC > 1) { load_chunk(1); cp_commit(); }

    const int rowA = warp_m * 64 + (lane & 15);
    const uint32_t maskA = (uint32_t)(rowA & 7) << 4;
    const uint32_t kbA = (uint32_t)(lane >> 4) * 16;
    const int rowB = warp_n * 32 + ((lane >> 4) & 1) * 8 + (lane & 7);
    const uint32_t maskB = (uint32_t)(lane & 7) << 4;
    const uint32_t kbB = (uint32_t)((lane >> 3) & 1) * 16;

    float acc[4][4][4] = {};

    for (int c = 0; c < NC; c++) {
        cp_wait1();
        __syncthreads();
        const uint32_t buf = sb + (uint32_t)(c & 1) * STAGE_B;
        const uint32_t aBase = buf + (uint32_t)rowA * 128;
        const uint32_t bBase = buf + 16384 + (uint32_t)rowB * 128;

#pragma unroll
        for (int k16 = 0; k16 < 4; k16++) {
            const uint32_t koffA = ((uint32_t)k16 * 32 + kbA) ^ maskA;
            const uint32_t koffB = ((uint32_t)k16 * 32 + kbB) ^ maskB;
            uint32_t ah[4][4], bh[4][2];
#pragma unroll
            for (int mi = 0; mi < 4; mi++)
                ldm_x4(ah[mi], aBase + mi * 2048 + koffA);
#pragma unroll
            for (int n4 = 0; n4 < 2; n4++) {
                uint32_t br[4];
                ldm_x4(br, bBase + n4 * 2048 + koffB);
                bh[n4 * 2 + 0][0] = br[0]; bh[n4 * 2 + 0][1] = br[1];
                bh[n4 * 2 + 1][0] = br[2]; bh[n4 * 2 + 1][1] = br[3];
            }
#pragma unroll
            for (int mi = 0; mi < 4; mi++)
#pragma unroll
                for (int ni = 0; ni < 4; ni++)
                    mma_f16(acc[mi][ni], ah[mi], bh[ni]);
        }
        __syncthreads();
        if (c + 2 < NC) load_chunk(c + 2);
        cp_commit();
    }

    const int rbase = m0 + warp_m * 64 + (lane >> 2);
    const int cbase = n0 + warp_n * 32 + (lane & 3) * 2;
#pragma unroll
    for (int mi = 0; mi < 4; mi++) {
#pragma unroll
        for (int half = 0; half < 2; half++) {
            const int row = rbase + mi * 16 + half * 8;
#pragma unroll
            for (int ni = 0; ni < 4; ni++) {
                const int col = cbase + ni * 8;
                float v0 = acc[mi][ni][half * 2 + 0];
                float v1 = acc[mi][ni][half * 2 + 1];
                if (bias) {
                    v0 += __ldg(&bias[col]);
                    v1 += __ldg(&bias[col + 1]);
                }
                if (GELU) {
                    float x3 = v0 * v0 * v0;
                    v0 = 0.5f * v0 * (1.0f + tanhf(0.7978845608028654f * (v0 + 0.044715f * x3)));
                    x3 = v1 * v1 * v1;
                    v1 = 0.5f * v1 * (1.0f + tanhf(0.7978845608028654f * (v1 + 0.044715f * x3)));
                }
                const size_t o = (size_t)z * cBS + (size_t)row * 512 + col;
                if (RESF) {
                    float2 q = *(const float2*)(resp + o);
                    v0 += q.x; v1 += q.y;
                }
                if (RESH) {
                    uint32_t rv = *(const uint32_t*)(resph + o);
                    __half2 rh = *reinterpret_cast<__half2*>(&rv);
                    v0 += __half2float(rh.x);
                    v1 += __half2float(rh.y);
                }
                if (WF32)
                    *(float2*)(C + o) = make_float2(v0, v1);
                if (WHALF)
                    *(uint32_t*)(Ch + o) = pack_hf2(v0, v1);
            }
        }
    }
}

// ------------------------- fused prep (single launch) ----------------------
__global__ __launch_bounds__(256)
void k_prep(const float* __restrict__ w_int, const float* __restrict__ alpha,
            const float* __restrict__ W1, const float* __restrict__ W2,
            const float* __restrict__ Wout,
            const float* __restrict__ emb, const float* __restrict__ pos,
            const float* __restrict__ sigma,
            hf* __restrict__ wh, hf* __restrict__ ebh, hf* __restrict__ kh)
{
    const int t = threadIdx.x;
    const int blk = blockIdx.x;
    if (blk < 1024) {
        const int z = blk >> 8;
        const int xy = blk & 255;
        if (z < 3) {
            __shared__ float tileW[32][33];
            const int tx = t & 31, ty = t >> 5;
            const int c0 = (xy & 15) * 32, r0 = (xy >> 4) * 32;
            const float* src = (z == 0) ? W1 : (z == 1) ? W2 : Wout;
            hf* dst = wh + (size_t)(z + 1) * 262144;
            const bool addI = (z == 2);
#pragma unroll
            for (int i = 0; i < 4; i++)
                tileW[ty + i * 8][tx] = src[(size_t)(r0 + ty + i * 8) * 512 + c0 + tx];
            __syncthreads();
#pragma unroll
            for (int i = 0; i < 4; i++) {
                float v = tileW[tx][ty + i * 8];
                if (addI && (r0 + tx) == (c0 + ty + i * 8)) v += 1.0f;
                dst[(size_t)(c0 + ty + i * 8) * 512 + r0 + tx] = __float2half_rn(v);
            }
        } else {
            __shared__ float sa[64];
            if (t < 64) sa[t] = alpha[t];
            __syncthreads();
#pragma unroll
            for (int it = 0; it < 4; it++) {
                int idx = xy * 1024 + it * 256 + t;
                int j = idx & 511;
                int i = idx >> 9;
                int k = i >> 6, d = i & 63;
                float s = 0.0f;
#pragma unroll
                for (int h = 0; h < 8; h++)
                    s = fmaf(sa[h * 8 + k], w_int[(size_t)(h * 64 + d) * 512 + j], s);
                wh[(size_t)j * 512 + i] = __float2half_rn(s);
            }
        }
    } else if (blk < 17408) {
        __shared__ float tileE[32][33];
        const int id = blk - 1024;
        const int tx = t & 31, ty = t >> 5;
        const int c0 = (id & 15) * 32;
        const int r0 = ((id >> 4) & 63) * 32;
        const int bz = id >> 10;
        const float* src = emb + (size_t)bz * Nn * Dd;
        hf* dst = ebh + (size_t)bz * Dd * Nn;
#pragma unroll
        for (int i = 0; i < 4; i++)
            tileE[ty + i * 8][tx] = src[(size_t)(r0 + ty + i * 8) * Dd + c0 + tx];
        __syncthreads();
#pragma unroll
        for (int i = 0; i < 4; i++) {
            float v = tileE[tx][ty + i * 8];
            dst[(size_t)(c0 + ty + i * 8) * Nn + r0 + tx] = __float2half_rn(v);
        }
    } else {
        size_t lin = (size_t)(blk - 17408) * 256 + t;
        int t8 = (int)(lin & 255);
        int m = (int)((lin >> 8) & 511);
        int b = (int)(lin >> 17);
        float s = __ldg(sigma);
        float inv = 1.0f / (2.0f * s * s);
        float gm = (float)m * (1.0f / 511.0f);
        const float* pp = pos + (size_t)b * Nn + t8 * 8;
        float4 p0 = *(const float4*)pp;
        float4 p1 = *(const float4*)(pp + 4);
        float d0 = gm - p0.x, d1 = gm - p0.y, d2 = gm - p0.z, d3 = gm - p0.w;
        float d4 = gm - p1.x, d5 = gm - p1.y, d6 = gm - p1.z, d7 = gm - p1.w;
        uint4 o4;
        o4.x = pack_hf2(__expf(-d0 * d0 * inv), __expf(-d1 * d1 * inv));
        o4.y = pack_hf2(__expf(-d2 * d2 * inv), __expf(-d3 * d3 * inv));
        o4.z = pack_hf2(__expf(-d4 * d4 * inv), __expf(-d5 * d5 * inv));
        o4.w = pack_hf2(__expf(-d6 * d6 * inv), __expf(-d7 * d7 * inv));
        *(uint4*)(kh + ((size_t)b * 512 + m) * 2048 + t8 * 8) = o4;
    }
}

// ------------------------- elementwise kernels -----------------------------
template <bool HOUT>
__global__ __launch_bounds__(256)
void k_diffuse3(const float* __restrict__ in, float* __restrict__ out,
                const float* __restrict__ coef, hf* __restrict__ oh)
{
    __shared__ float s[512 * 8];
    const int t = threadIdx.x;
    const int b = blockIdx.x >> 6;
    const int d0 = (blockIdx.x & 63) * 8;
    const int dl = t & 7;
    const size_t gbase = ((size_t)b * Mm) * Dd + d0;
    const float c = DT_C * __ldg(&coef[d0 + dl]);
#pragma unroll
    for (int i = 0; i < 16; i++) {
        int idx = t + i * 256;
        s[idx] = in[gbase + (size_t)(idx >> 3) * Dd + dl];
    }
    __syncthreads();
#pragma unroll
    for (int step = 0; step < 3; step++) {
        float nv[16];
#pragma unroll
        for (int i = 0; i < 16; i++) {
            int idx = t + i * 256;
            int m = idx >> 3;
            float v = s[idx];
            float l = (m > 0) ? s[idx - 8] : v;
            float r = (m < 511) ? s[idx + 8] : v;
            nv[i] = fmaf(c, l + r - 2.0f * v, v);
        }
        __syncthreads();
#pragma unroll
        for (int i = 0; i < 16; i++) s[t + i * 256] = nv[i];
        __syncthreads();
    }
#pragma unroll
    for (int i = 0; i < 16; i++) {
        int idx = t + i * 256;
        size_t g = gbase + (size_t)(idx >> 3) * Dd + dl;
        float v = s[idx];
        out[g] = v;
        if (HOUT) oh[g] = __float2half_rn(v);
    }
}

__global__ __launch_bounds__(128)
void k_sample_ln(const float* __restrict__ pos, const float* __restrict__ emb,
                 const float* __restrict__ field,
                 const float* __restrict__ gam, const float* __restrict__ bet,
                 hf* __restrict__ oh)
{
    __shared__ float ssum[4], ssq[4], sstat[2];
    int row = blockIdx.x;
    int b = row >> 11;
    float p = __ldg(&pos[row]);
    float u = fminf(fmaxf(p, 0.0f), 1.0f) * (float)(Mm - 1);
    int i0 = (int)u;
    if (i0 > Mm - 2) i0 = Mm - 2;
    float w = u - (float)i0;

    const float* f0 = field + ((size_t)b * Mm + i0) * Dd;
    int t = threadIdx.x;
    int d0 = t * 4;
    float4 a = *(const float4*)(f0 + d0);
    float4 bb = *(const float4*)(f0 + Dd + d0);
    float4 e = *(const float4*)(emb + (size_t)row * Dd + d0);
    float x[4];
    x[0] = fmaf(w, bb.x - a.x, a.x) + e.x;
    x[1] = fmaf(w, bb.y - a.y, a.y) + e.y;
    x[2] = fmaf(w, bb.z - a.z, a.z) + e.z;
    x[3] = fmaf(w, bb.w - a.w, a.w) + e.w;
    float sum = x[0] + x[1] + x[2] + x[3];
    float sq = fmaf(x[0], x[0], fmaf(x[1], x[1], fmaf(x[2], x[2], x[3] * x[3])));
#pragma unroll
    for (int o = 16; o > 0; o >>= 1) {
        sum += __shfl_down_sync(0xffffffffu, sum, o);
        sq += __shfl_down_sync(0xffffffffu, sq, o);
    }
    int wd = t >> 5, ln = t & 31;
    if (ln == 0) { ssum[wd] = sum; ssq[wd] = sq; }
    __syncthreads();
    if (t == 0) {
        float S = ssum[0] + ssum[1] + ssum[2] + ssum[3];
        float Q = ssq[0] + ssq[1] + ssq[2] + ssq[3];
        float mu = S * (1.0f / Dd);
        float var = Q * (1.0f / Dd) - mu * mu;
        sstat[0] = mu;
        sstat[1] = rsqrtf(var + 1e-5f);
    }
    __syncthreads();
    float mu = sstat[0], inv = sstat[1];
    float4 g = *(const float4*)(gam + d0);
    float4 be = *(const float4*)(bet + d0);
    float y0 = (x[0] - mu) * inv * g.x + be.x;
    float y1 = (x[1] - mu) * inv * g.y + be.y;
    float y2 = (x[2] - mu) * inv * g.z + be.z;
    float y3 = (x[3] - mu) * inv * g.w + be.w;
    size_t o = (size_t)row * Dd + d0;
    uint2 hh;
    hh.x = pack_hf2(y0, y1); hh.y = pack_hf2(y2, y3);
    *(uint2*)(oh + o) = hh;
}

__global__ __launch_bounds__(128)
void k_ln2(const hf* __restrict__ pre, const float* __restrict__ gam,
           const float* __restrict__ bet, float* __restrict__ out)
{
    __shared__ float ssum[4], ssq[4], sstat[2];
    int row = blockIdx.x;
    int t = threadIdx.x;
    int d0 = t * 4;
    size_t o = (size_t)row * Dd + d0;
    uint2 hv = *(const uint2*)(pre + o);
    __half2 h01 = *reinterpret_cast<__half2*>(&hv.x);
    __half2 h23 = *reinterpret_cast<__half2*>(&hv.y);
    float x[4] = {__half2float(h01.x), __half2float(h01.y),
                  __half2float(h23.x), __half2float(h23.y)};
    float sum = x[0] + x[1] + x[2] + x[3];
    float sq = fmaf(x[0], x[0], fmaf(x[1], x[1], fmaf(x[2], x[2], x[3] * x[3])));
#pragma unroll
    for (int s = 16; s > 0; s >>= 1) {
        sum += __shfl_down_sync(0xffffffffu, sum, s);
        sq += __shfl_down_sync(0xffffffffu, sq, s);
    }
    int wd = t >> 5, ln = t & 31;
    if (ln == 0) { ssum[wd] = sum; ssq[wd] = sq; }
    __syncthreads();
    if (t == 0) {
        float S = ssum[0] + ssum[1] + ssum[2] + ssum[3];
        float Q = ssq[0] + ssq[1] + ssq[2] + ssq[3];
        float mu = S * (1.0f / Dd);
        float var = Q * (1.0f / Dd) - mu * mu;
        sstat[0] = mu;
        sstat[1] = rsqrtf(var + 1e-5f);
    }
    __syncthreads();
    float mu = sstat[0], inv = sstat[1];
    float4 g = *(const float4*)(gam + d0);
    float4 be = *(const float4*)(bet + d0);
    *(float4*)(out + o) = make_float4(
        (x[0] - mu) * inv * g.x + be.x, (x[1] - mu) * inv * g.y + be.y,
        (x[2] - mu) * inv * g.z + be.z, (x[3] - mu) * inv * g.w + be.w);
}

// ---------------------------------------------------------------------------
extern "C" void kernel_launch(void* const* d_in, const int* in_sizes, int n_in,
                              void* d_out, int out_size)
{
    const float* emb   = (const float*)d_in[0];
    const float* pos   = (const float*)d_in[1];
    const float* sigma = (const float*)d_in[2];
    const float* alpha = (const float*)d_in[3];
    const float* w_int = (const float*)d_in[4];
    const float* b_int = (const float*)d_in[5];
    const float* dcoef = (const float*)d_in[6];
    const float* W1    = (const float*)d_in[7];
    const float* b1    = (const float*)d_in[8];
    const float* W2    = (const float*)d_in[9];
    const float* b2    = (const float*)d_in[10];
    const float* ecoef = (const float*)d_in[11];
    const float* ln1g  = (const float*)d_in[12];
    const float* ln1b  = (const float*)d_in[13];
    const float* Wout  = (const float*)d_in[14];
    const float* bout  = (const float*)d_in[15];
    const float* ln2g  = (const float*)d_in[16];
    const float* ln2b  = (const float*)d_in[17];
    float* out = (float*)d_out;

    hf *h1, *h2, *ebh, *wh;
    float *field, *tmp2;
    cudaGetSymbolAddress((void**)&h1, g_h1);
    cudaGetSymbolAddress((void**)&h2, g_h2);
    cudaGetSymbolAddress((void**)&ebh, g_ebh);
    cudaGetSymbolAddress((void**)&wh, g_wh);
    cudaGetSymbolAddress((void**)&field, g_field);
    cudaGetSymbolAddress((void**)&tmp2, g_tmp2);

    cudaFuncSetAttribute(k_gemm_mma<false, false, false, false, true>,
                         cudaFuncAttributeMaxDynamicSharedMemorySize, SMEM_SZ);
    cudaFuncSetAttribute(k_gemm_mma<false, false, true, true, false>,
                         cudaFuncAttributeMaxDynamicSharedMemorySize, SMEM_SZ);
    cudaFuncSetAttribute(k_gemm_mma<true, false, false, false, true>,
                         cudaFuncAttributeMaxDynamicSharedMemorySize, SMEM_SZ);
    cudaFuncSetAttribute(k_gemm_mma<false, true, false, true, false>,
                         cudaFuncAttributeMaxDynamicSharedMemorySize, SMEM_SZ);

    // 0) fused prep: weights (fold W', W1^T, W2^T, (Wout+I)^T), embT, K-RBF->h1
    k_prep<<<25600, 256>>>(w_int, alpha, W1, W2, Wout, emb, pos, sigma,
                           wh, ebh, h1);

    // 1) field(fp16) = K @ emb^T' -> h2    [batched, Kdim=2048]
    k_gemm_mma<false, false, false, false, true><<<dim3(4, 4, 16), 256, SMEM_SZ>>>(
        h1, 2048, (size_t)512 * 2048,
        ebh, 2048, (size_t)512 * 2048,
        nullptr, nullptr, nullptr, nullptr, h2, (size_t)512 * 512, 2048);

    // 2) tmp2 = field(h2) + field @ W' + b_int   (residual from fp16 field)
    k_gemm_mma<false, false, true, true, false><<<dim3(64, 4, 1), 256, SMEM_SZ>>>(
        h2, 512, 0, wh + 0 * 262144, 512, 0,
        b_int, nullptr, h2, tmp2, nullptr, 0, 512);

    // 3) diffusion x3 -> field (+ fp16 h2)
    k_diffuse3<true><<<Bn * 64, 256>>>(tmp2, field, dcoef, h2);

    // 4) gelu(field @ W1 + b1) -> h1 (fp16)
    k_gemm_mma<true, false, false, false, true><<<dim3(64, 4, 1), 256, SMEM_SZ>>>(
        h2, 512, 0, wh + 1 * 262144, 512, 0,
        b1, nullptr, nullptr, nullptr, h1, 0, 512);

    // 5) tmp2 = field + gelu @ W2 + b2
    k_gemm_mma<false, true, false, true, false><<<dim3(64, 4, 1), 256, SMEM_SZ>>>(
        h1, 512, 0, wh + 2 * 262144, 512, 0,
        b2, field, nullptr, tmp2, nullptr, 0, 512);

    // 6) diffusion x3 -> field
    k_diffuse3<false><<<Bn * 64, 256>>>(tmp2, field, ecoef, nullptr);

    // 7) enh = LN1(sample(field) + emb) -> h1 (fp16)
    k_sample_ln<<<Bn * Nn, 128>>>(pos, emb, field, ln1g, ln1b, h1);

    // 8) preLN2 = enh @ (Wout + I) + bout -> ebh (fp16; residual folded)
    k_gemm_mma<false, false, false, false, true><<<dim3(256, 4, 1), 256, SMEM_SZ>>>(
        h1, 512, 0, wh + 3 * 262144, 512, 0,
        bout, nullptr, nullptr, nullptr, ebh, 0, 512);

    // 9) out = LN2(preLN2)
    k_ln2<<<Bn * Nn, 128>>>(ebh, ln2g, ln2b, out);
}

// round 14
// speedup vs baseline: 1.1252x; 1.0159x over previous
#include <cuda_runtime.h>
#include <cuda_fp16.h>
#include <math.h>
#include <stdint.h>

#define Bn 16
#define Nn 2048
#define Dd 512
#define Mm 512
#define DT_C 0.01f

typedef __half hf;

// ------------------------- device scratch (no runtime alloc) ---------------
__device__ hf g_h1[(size_t)32768 * 512];   // 32MB  (K-RBF A / gelu / enh)
__device__ hf g_h2[(size_t)8192 * 512];    // 8MB   (field fp16)
__device__ hf g_ebh[(size_t)Bn * Dd * Nn]; // 32MB  embT [b,d,t]; later pre-LN2 fp16
__device__ hf g_wh[4][512 * 512];          // 2MB   [0]=W' fold, [1]=W1^T, [2]=W2^T, [3]=(Wout+I)^T
__device__ hf g_t2h[(size_t)8192 * 512];   // 8MB   fp16 GEMM2/5 outputs
__device__ float g_field[(size_t)Bn * Mm * Dd]; // 16MB (post-diffuse2 only)

// ------------------------- helpers -----------------------------------------
__device__ __forceinline__ uint32_t smem_u32(const void* p) {
    uint32_t a;
    asm("{ .reg .u64 t; cvta.to.shared.u64 t, %1; cvt.u32.u64 %0, t; }" : "=r"(a) : "l"(p));
    return a;
}
__device__ __forceinline__ uint32_t pack_hf2(float a, float b) {
    __half2 t = __floats2half2_rn(a, b);
    return *reinterpret_cast<uint32_t*>(&t);
}
__device__ __forceinline__ void cp16(uint32_t dst, const void* src) {
    asm volatile("cp.async.cg.shared.global [%0], [%1], 16;" :: "r"(dst), "l"(src));
}
__device__ __forceinline__ void cp_commit() {
    asm volatile("cp.async.commit_group;");
}
__device__ __forceinline__ void cp_wait1() {
    asm volatile("cp.async.wait_group 1;");
}
__device__ __forceinline__ void ldm_x4(uint32_t* r, uint32_t a) {
    asm volatile("ldmatrix.sync.aligned.m8n8.x4.shared.b16 {%0,%1,%2,%3}, [%4];"
                 : "=r"(r[0]), "=r"(r[1]), "=r"(r[2]), "=r"(r[3]) : "r"(a));
}
__device__ __forceinline__ void mma_f16(float* c, const uint32_t* a, const uint32_t* b) {
    asm volatile(
        "mma.sync.aligned.m16n8k16.row.col.f32.f16.f16.f32 "
        "{%0,%1,%2,%3}, {%4,%5,%6,%7}, {%8,%9}, {%0,%1,%2,%3};"
        : "+f"(c[0]), "+f"(c[1]), "+f"(c[2]), "+f"(c[3])
        : "r"(a[0]), "r"(a[1]), "r"(a[2]), "r"(a[3]), "r"(b[0]), "r"(b[1]));
}

// ------------------------- HMMA GEMM (fp16, single-pass, 2-stage) -----------
#define STAGE_B 32768u
#define SMEM_SZ (2 * 32768)

// All outputs fp16. RESH: add fp16 residual from resph.
template <bool GELU, bool RESH>
__global__ __launch_bounds__(256, 2)
void k_gemm_mma(const hf* __restrict__ A, size_t aRS, size_t aBS,
                const hf* __restrict__ B, size_t bRS, size_t bBS,
                const float* __restrict__ bias, const hf* __restrict__ resph,
                hf* __restrict__ Ch, size_t cBS, int Kdim)
{
    extern __shared__ char smem[];
    const uint32_t sb = smem_u32(smem);
    const int t = threadIdx.x;
    const int wid = t >> 5;
    const int lane = t & 31;
    const int warp_m = wid & 1;
    const int warp_n = wid >> 1;

    const int m0 = blockIdx.x * 128;
    const int n0 = blockIdx.y * 128;
    const int z = blockIdx.z;

    const hf* pA = A + (size_t)z * aBS;
    const hf* pB = B + (size_t)z * bBS;

    const int NC = Kdim >> 6;

    auto load_chunk = [&](int c) {
        const uint32_t buf = sb + (uint32_t)(c & 1) * STAGE_B;
        const int k0 = c << 6;
#pragma unroll
        for (int i = 0; i < 4; i++) {
            int id = t + i * 256;
            int row = id >> 3;
            int seg = id & 7;
            uint32_t soff = (uint32_t)row * 128 + (uint32_t)((seg * 16) ^ ((row & 7) << 4));
            cp16(buf + soff,         pA + (size_t)(m0 + row) * aRS + k0 + seg * 8);
            cp16(buf + 16384 + soff, pB + (size_t)(n0 + row) * bRS + k0 + seg * 8);
        }
    };

    load_chunk(0); cp_commit();
    if (NC > 1) { load_chunk(1); cp_commit(); }

    const int rowA = warp_m * 64 + (lane & 15);
    const uint32_t maskA = (uint32_t)(rowA & 7) << 4;
    const uint32_t kbA = (uint32_t)(lane >> 4) * 16;
    const int rowB = warp_n * 32 + ((lane >> 4) & 1) * 8 + (lane & 7);
    const uint32_t maskB = (uint32_t)(lane & 7) << 4;
    const uint32_t kbB = (uint32_t)((lane >> 3) & 1) * 16;

    float acc[4][4][4] = {};

    for (int c = 0; c < NC; c++) {
        cp_wait1();
        __syncthreads();
        const uint32_t buf = sb + (uint32_t)(c & 1) * STAGE_B;
        const uint32_t aBase = buf + (uint32_t)rowA * 128;
        const uint32_t bBase = buf + 16384 + (uint32_t)rowB * 128;

#pragma unroll
        for (int k16 = 0; k16 < 4; k16++) {
            const uint32_t koffA = ((uint32_t)k16 * 32 + kbA) ^ maskA;
            const uint32_t koffB = ((uint32_t)k16 * 32 + kbB) ^ maskB;
            uint32_t ah[4][4], bh[4][2];
#pragma unroll
            for (int mi = 0; mi < 4; mi++)
                ldm_x4(ah[mi], aBase + mi * 2048 + koffA);
#pragma unroll
            for (int n4 = 0; n4 < 2; n4++) {
                uint32_t br[4];
                ldm_x4(br, bBase + n4 * 2048 + koffB);
                bh[n4 * 2 + 0][0] = br[0]; bh[n4 * 2 + 0][1] = br[1];
                bh[n4 * 2 + 1][0] = br[2]; bh[n4 * 2 + 1][1] = br[3];
            }
#pragma unroll
            for (int mi = 0; mi < 4; mi++)
#pragma unroll
                for (int ni = 0; ni < 4; ni++)
                    mma_f16(acc[mi][ni], ah[mi], bh[ni]);
        }
        __syncthreads();
        if (c + 2 < NC) load_chunk(c + 2);
        cp_commit();
    }

    const int rbase = m0 + warp_m * 64 + (lane >> 2);
    const int cbase = n0 + warp_n * 32 + (lane & 3) * 2;
#pragma unroll
    for (int mi = 0; mi < 4; mi++) {
#pragma unroll
        for (int half = 0; half < 2; half++) {
            const int row = rbase + mi * 16 + half * 8;
#pragma unroll
            for (int ni = 0; ni < 4; ni++) {
                const int col = cbase + ni * 8;
                float v0 = acc[mi][ni][half * 2 + 0];
                float v1 = acc[mi][ni][half * 2 + 1];
                if (bias) {
                    v0 += __ldg(&bias[col]);
                    v1 += __ldg(&bias[col + 1]);
                }
                if (GELU) {
                    float x3 = v0 * v0 * v0;
                    v0 = 0.5f * v0 * (1.0f + tanhf(0.7978845608028654f * (v0 + 0.044715f * x3)));
                    x3 = v1 * v1 * v1;
                    v1 = 0.5f * v1 * (1.0f + tanhf(0.7978845608028654f * (v1 + 0.044715f * x3)));
                }
                const size_t o = (size_t)z * cBS + (size_t)row * 512 + col;
                if (RESH) {
                    uint32_t rv = *(const uint32_t*)(resph + o);
                    __half2 rh = *reinterpret_cast<__half2*>(&rv);
                    v0 += __half2float(rh.x);
                    v1 += __half2float(rh.y);
                }
                *(uint32_t*)(Ch + o) = pack_hf2(v0, v1);
            }
        }
    }
}

// ------------------------- fused prep (single launch) ----------------------
__global__ __launch_bounds__(256)
void k_prep(const float* __restrict__ w_int, const float* __restrict__ alpha,
            const float* __restrict__ W1, const float* __restrict__ W2,
            const float* __restrict__ Wout,
            const float* __restrict__ emb, const float* __restrict__ pos,
            const float* __restrict__ sigma,
            hf* __restrict__ wh, hf* __restrict__ ebh, hf* __restrict__ kh)
{
    const int t = threadIdx.x;
    const int blk = blockIdx.x;
    if (blk < 1024) {
        const int z = blk >> 8;
        const int xy = blk & 255;
        if (z < 3) {
            __shared__ float tileW[32][33];
            const int tx = t & 31, ty = t >> 5;
            const int c0 = (xy & 15) * 32, r0 = (xy >> 4) * 32;
            const float* src = (z == 0) ? W1 : (z == 1) ? W2 : Wout;
            hf* dst = wh + (size_t)(z + 1) * 262144;
            const bool addI = (z == 2);
#pragma unroll
            for (int i = 0; i < 4; i++)
                tileW[ty + i * 8][tx] = src[(size_t)(r0 + ty + i * 8) * 512 + c0 + tx];
            __syncthreads();
#pragma unroll
            for (int i = 0; i < 4; i++) {
                float v = tileW[tx][ty + i * 8];
                if (addI && (r0 + tx) == (c0 + ty + i * 8)) v += 1.0f;
                dst[(size_t)(c0 + ty + i * 8) * 512 + r0 + tx] = __float2half_rn(v);
            }
        } else {
            __shared__ float sa[64];
            if (t < 64) sa[t] = alpha[t];
            __syncthreads();
#pragma unroll
            for (int it = 0; it < 4; it++) {
                int idx = xy * 1024 + it * 256 + t;
                int j = idx & 511;
                int i = idx >> 9;
                int k = i >> 6, d = i & 63;
                float s = 0.0f;
#pragma unroll
                for (int h = 0; h < 8; h++)
                    s = fmaf(sa[h * 8 + k], w_int[(size_t)(h * 64 + d) * 512 + j], s);
                wh[(size_t)j * 512 + i] = __float2half_rn(s);
            }
        }
    } else if (blk < 17408) {
        __shared__ float tileE[32][33];
        const int id = blk - 1024;
        const int tx = t & 31, ty = t >> 5;
        const int c0 = (id & 15) * 32;
        const int r0 = ((id >> 4) & 63) * 32;
        const int bz = id >> 10;
        const float* src = emb + (size_t)bz * Nn * Dd;
        hf* dst = ebh + (size_t)bz * Dd * Nn;
#pragma unroll
        for (int i = 0; i < 4; i++)
            tileE[ty + i * 8][tx] = src[(size_t)(r0 + ty + i * 8) * Dd + c0 + tx];
        __syncthreads();
#pragma unroll
        for (int i = 0; i < 4; i++) {
            float v = tileE[tx][ty + i * 8];
            dst[(size_t)(c0 + ty + i * 8) * Nn + r0 + tx] = __float2half_rn(v);
        }
    } else {
        size_t lin = (size_t)(blk - 17408) * 256 + t;
        int t8 = (int)(lin & 255);
        int m = (int)((lin >> 8) & 511);
        int b = (int)(lin >> 17);
        float s = __ldg(sigma);
        float inv = 1.0f / (2.0f * s * s);
        float gm = (float)m * (1.0f / 511.0f);
        const float* pp = pos + (size_t)b * Nn + t8 * 8;
        float4 p0 = *(const float4*)pp;
        float4 p1 = *(const float4*)(pp + 4);
        float d0 = gm - p0.x, d1 = gm - p0.y, d2 = gm - p0.z, d3 = gm - p0.w;
        float d4 = gm - p1.x, d5 = gm - p1.y, d6 = gm - p1.z, d7 = gm - p1.w;
        uint4 o4;
        o4.x = pack_hf2(__expf(-d0 * d0 * inv), __expf(-d1 * d1 * inv));
        o4.y = pack_hf2(__expf(-d2 * d2 * inv), __expf(-d3 * d3 * inv));
        o4.z = pack_hf2(__expf(-d4 * d4 * inv), __expf(-d5 * d5 * inv));
        o4.w = pack_hf2(__expf(-d6 * d6 * inv), __expf(-d7 * d7 * inv));
        *(uint4*)(kh + ((size_t)b * 512 + m) * 2048 + t8 * 8) = o4;
    }
}

// ------------------------- fp16-I/O diffusion ------------------------------
// One block = one (batch, 8 d-columns) strip over all 512 m; 3 Euler steps.
// Input fp16; outputs: optional f32 (F32OUT) and/or fp16 (HOUT).
template <bool F32OUT, bool HOUT>
__global__ __launch_bounds__(256)
void k_diffuse3h(const hf* __restrict__ in, float* __restrict__ out,
                 const float* __restrict__ coef, hf* __restrict__ oh)
{
    __shared__ float s[512 * 8];
    const int t = threadIdx.x;
    const int b = blockIdx.x >> 6;
    const int d0 = (blockIdx.x & 63) * 8;
    const int dl = (t & 3) * 2;         // d-pair within strip
    const int mb = t >> 2;              // 0..63
    const size_t gbase = ((size_t)b * Mm) * Dd + d0 + dl;
    const float c0c = DT_C * __ldg(&coef[d0 + dl]);
    const float c1c = DT_C * __ldg(&coef[d0 + dl + 1]);

#pragma unroll
    for (int i = 0; i < 8; i++) {
        int m = mb + i * 64;
        uint32_t v = *(const uint32_t*)(in + gbase + (size_t)m * Dd);
        __half2 h = *reinterpret_cast<__half2*>(&v);
        s[m * 8 + dl]     = __half2float(h.x);
        s[m * 8 + dl + 1] = __half2float(h.y);
    }
    __syncthreads();

#pragma unroll
    for (int step = 0; step < 3; step++) {
        float nv0[8], nv1[8];
#pragma unroll
        for (int i = 0; i < 8; i++) {
            int m = mb + i * 64;
            int idx = m * 8 + dl;
            float v0 = s[idx], v1 = s[idx + 1];
            float l0 = (m > 0)   ? s[idx - 8] : v0;
            float r0 = (m < 511) ? s[idx + 8] : v0;
            float l1 = (m > 0)   ? s[idx - 7] : v1;
            float r1 = (m < 511) ? s[idx + 9] : v1;
            nv0[i] = fmaf(c0c, l0 + r0 - 2.0f * v0, v0);
            nv1[i] = fmaf(c1c, l1 + r1 - 2.0f * v1, v1);
        }
        __syncthreads();
#pragma unroll
        for (int i = 0; i < 8; i++) {
            int idx = (mb + i * 64) * 8 + dl;
            s[idx] = nv0[i];
            s[idx + 1] = nv1[i];
        }
        __syncthreads();
    }

#pragma unroll
    for (int i = 0; i < 8; i++) {
        int m = mb + i * 64;
        int idx = m * 8 + dl;
        float v0 = s[idx], v1 = s[idx + 1];
        size_t g = gbase + (size_t)m * Dd;
        if (F32OUT) *(float2*)(out + g) = make_float2(v0, v1);
        if (HOUT)   *(uint32_t*)(oh + g) = pack_hf2(v0, v1);
    }
}

// sample + residual + LN1 -> fp16 (enh)
__global__ __launch_bounds__(128)
void k_sample_ln(const float* __restrict__ pos, const float* __restrict__ emb,
                 const float* __restrict__ field,
                 const float* __restrict__ gam, const float* __restrict__ bet,
                 hf* __restrict__ oh)
{
    __shared__ float ssum[4], ssq[4], sstat[2];
    int row = blockIdx.x;
    int b = row >> 11;
    float p = __ldg(&pos[row]);
    float u = fminf(fmaxf(p, 0.0f), 1.0f) * (float)(Mm - 1);
    int i0 = (int)u;
    if (i0 > Mm - 2) i0 = Mm - 2;
    float w = u - (float)i0;

    const float* f0 = field + ((size_t)b * Mm + i0) * Dd;
    int t = threadIdx.x;
    int d0 = t * 4;
    float4 a = *(const float4*)(f0 + d0);
    float4 bb = *(const float4*)(f0 + Dd + d0);
    float4 e = *(const float4*)(emb + (size_t)row * Dd + d0);
    float x[4];
    x[0] = fmaf(w, bb.x - a.x, a.x) + e.x;
    x[1] = fmaf(w, bb.y - a.y, a.y) + e.y;
    x[2] = fmaf(w, bb.z - a.z, a.z) + e.z;
    x[3] = fmaf(w, bb.w - a.w, a.w) + e.w;
    float sum = x[0] + x[1] + x[2] + x[3];
    float sq = fmaf(x[0], x[0], fmaf(x[1], x[1], fmaf(x[2], x[2], x[3] * x[3])));
#pragma unroll
    for (int o = 16; o > 0; o >>= 1) {
        sum += __shfl_down_sync(0xffffffffu, sum, o);
        sq += __shfl_down_sync(0xffffffffu, sq, o);
    }
    int wd = t >> 5, ln = t & 31;
    if (ln == 0) { ssum[wd] = sum; ssq[wd] = sq; }
    __syncthreads();
    if (t == 0) {
        float S = ssum[0] + ssum[1] + ssum[2] + ssum[3];
        float Q = ssq[0] + ssq[1] + ssq[2] + ssq[3];
        float mu = S * (1.0f / Dd);
        float var = Q * (1.0f / Dd) - mu * mu;
        sstat[0] = mu;
        sstat[1] = rsqrtf(var + 1e-5f);
    }
    __syncthreads();
    float mu = sstat[0], inv = sstat[1];
    float4 g = *(const float4*)(gam + d0);
    float4 be = *(const float4*)(bet + d0);
    float y0 = (x[0] - mu) * inv * g.x + be.x;
    float y1 = (x[1] - mu) * inv * g.y + be.y;
    float y2 = (x[2] - mu) * inv * g.z + be.z;
    float y3 = (x[3] - mu) * inv * g.w + be.w;
    size_t o = (size_t)row * Dd + d0;
    uint2 hh;
    hh.x = pack_hf2(y0, y1); hh.y = pack_hf2(y2, y3);
    *(uint2*)(oh + o) = hh;
}

// final LN2: reads fp16 pre-LN (residual folded into Wout+I), writes f32 out
__global__ __launch_bounds__(128)
void k_ln2(const hf* __restrict__ pre, const float* __restrict__ gam,
           const float* __restrict__ bet, float* __restrict__ out)
{
    __shared__ float ssum[4], ssq[4], sstat[2];
    int row = blockIdx.x;
    int t = threadIdx.x;
    int d0 = t * 4;
    size_t o = (size_t)row * Dd + d0;
    uint2 hv = *(const uint2*)(pre + o);
    __half2 h01 = *reinterpret_cast<__half2*>(&hv.x);
    __half2 h23 = *reinterpret_cast<__half2*>(&hv.y);
    float x[4] = {__half2float(h01.x), __half2float(h01.y),
                  __half2float(h23.x), __half2float(h23.y)};
    float sum = x[0] + x[1] + x[2] + x[3];
    float sq = fmaf(x[0], x[0], fmaf(x[1], x[1], fmaf(x[2], x[2], x[3] * x[3])));
#pragma unroll
    for (int s = 16; s > 0; s >>= 1) {
        sum += __shfl_down_sync(0xffffffffu, sum, s);
        sq += __shfl_down_sync(0xffffffffu, sq, s);
    }
    int wd = t >> 5, ln = t & 31;
    if (ln == 0) { ssum[wd] = sum; ssq[wd] = sq; }
    __syncthreads();
    if (t == 0) {
        float S = ssum[0] + ssum[1] + ssum[2] + ssum[3];
        float Q = ssq[0] + ssq[1] + ssq[2] + ssq[3];
        float mu = S * (1.0f / Dd);
        float var = Q * (1.0f / Dd) - mu * mu;
        sstat[0] = mu;
        sstat[1] = rsqrtf(var + 1e-5f);
    }
    __syncthreads();
    float mu = sstat[0], inv = sstat[1];
    float4 g = *(const float4*)(gam + d0);
    float4 be = *(const float4*)(bet + d0);
    *(float4*)(out + o) = make_float4(
        (x[0] - mu) * inv * g.x + be.x, (x[1] - mu) * inv * g.y + be.y,
        (x[2] - mu) * inv * g.z + be.z, (x[3] - mu) * inv * g.w + be.w);
}

// ---------------------------------------------------------------------------
extern "C" void kernel_launch(void* const* d_in, const int* in_sizes, int n_in,
                              void* d_out, int out_size)
{
    const float* emb   = (const float*)d_in[0];
    const float* pos   = (const float*)d_in[1];
    const float* sigma = (const float*)d_in[2];
    const float* alpha = (const float*)d_in[3];
    const float* w_int = (const float*)d_in[4];
    const float* b_int = (const float*)d_in[5];
    const float* dcoef = (const float*)d_in[6];
    const float* W1    = (const float*)d_in[7];
    const float* b1    = (const float*)d_in[8];
    const float* W2    = (const float*)d_in[9];
    const float* b2    = (const float*)d_in[10];
    const float* ecoef = (const float*)d_in[11];
    const float* ln1g  = (const float*)d_in[12];
    const float* ln1b  = (const float*)d_in[13];
    const float* Wout  = (const float*)d_in[14];
    const float* bout  = (const float*)d_in[15];
    const float* ln2g  = (const float*)d_in[16];
    const float* ln2b  = (const float*)d_in[17];
    float* out = (float*)d_out;

    hf *h1, *h2, *ebh, *wh, *t2h;
    float *field;
    cudaGetSymbolAddress((void**)&h1, g_h1);
    cudaGetSymbolAddress((void**)&h2, g_h2);
    cudaGetSymbolAddress((void**)&ebh, g_ebh);
    cudaGetSymbolAddress((void**)&wh, g_wh);
    cudaGetSymbolAddress((void**)&t2h, g_t2h);
    cudaGetSymbolAddress((void**)&field, g_field);

    cudaFuncSetAttribute(k_gemm_mma<false, false>,
                         cudaFuncAttributeMaxDynamicSharedMemorySize, SMEM_SZ);
    cudaFuncSetAttribute(k_gemm_mma<false, true>,
                         cudaFuncAttributeMaxDynamicSharedMemorySize, SMEM_SZ);
    cudaFuncSetAttribute(k_gemm_mma<true, false>,
                         cudaFuncAttributeMaxDynamicSharedMemorySize, SMEM_SZ);

    // 0) fused prep: weights (fold W', W1^T, W2^T, (Wout+I)^T), embT, K-RBF->h1
    k_prep<<<25600, 256>>>(w_int, alpha, W1, W2, Wout, emb, pos, sigma,
                           wh, ebh, h1);

    // 1) field(fp16) = K @ emb^T' -> h2    [batched, Kdim=2048]
    k_gemm_mma<false, false><<<dim3(4, 4, 16), 256, SMEM_SZ>>>(
        h1, 2048, (size_t)512 * 2048,
        ebh, 2048, (size_t)512 * 2048,
        nullptr, nullptr, h2, (size_t)512 * 512, 2048);

    // 2) t2h = field + field @ W' + b_int   (fp16 out, fp16 residual)
    k_gemm_mma<false, true><<<dim3(64, 4, 1), 256, SMEM_SZ>>>(
        h2, 512, 0, wh + 0 * 262144, 512, 0,
        b_int, h2, t2h, 0, 512);

    // 3) diffusion x3 (dcoef): t2h -> h2 (fp16 only)
    k_diffuse3h<false, true><<<Bn * 64, 256>>>(t2h, nullptr, dcoef, h2);

    // 4) gelu(field @ W1 + b1) -> h1 (fp16)
    k_gemm_mma<true, false><<<dim3(64, 4, 1), 256, SMEM_SZ>>>(
        h2, 512, 0, wh + 1 * 262144, 512, 0,
        b1, nullptr, h1, 0, 512);

    // 5) t2h = field(h2) + gelu @ W2 + b2   (fp16 out, fp16 residual)
    k_gemm_mma<false, true><<<dim3(64, 4, 1), 256, SMEM_SZ>>>(
        h1, 512, 0, wh + 2 * 262144, 512, 0,
        b2, h2, t2h, 0, 512);

    // 6) diffusion x3 (ecoef): t2h -> field (f32, for exact sampling)
    k_diffuse3h<true, false><<<Bn * 64, 256>>>(t2h, field, ecoef, nullptr);

    // 7) enh = LN1(sample(field) + emb) -> h1 (fp16)
    k_sample_ln<<<Bn * Nn, 128>>>(pos, emb, field, ln1g, ln1b, h1);

    // 8) preLN2 = enh @ (Wout + I) + bout -> ebh (fp16; residual folded)
    k_gemm_mma<false, false><<<dim3(256, 4, 1), 256, SMEM_SZ>>>(
        h1, 512, 0, wh + 3 * 262144, 512, 0,
        bout, nullptr, ebh, 0, 512);

    // 9) out = LN2(preLN2)
    k_ln2<<<Bn * Nn, 128>>>(ebh, ln2g, ln2b, out);
}

// round 15
// speedup vs baseline: 1.1448x; 1.0174x over previous
#include <cuda_runtime.h>
#include <cuda_fp16.h>
#include <math.h>
#include <stdint.h>

#define Bn 16
#define Nn 2048
#define Dd 512
#define Mm 512
#define DT_C 0.01f

typedef __half hf;

// ------------------------- device scratch (no runtime alloc) ---------------
__device__ hf g_h1[(size_t)32768 * 512];   // 32MB  (K-RBF A / gelu / enh)
__device__ hf g_h2[(size_t)8192 * 512];    // 8MB   (field fp16)
__device__ hf g_ebh[(size_t)Bn * Dd * Nn]; // 32MB  embT [b,d,t]; later pre-LN2 fp16
__device__ hf g_wh[4][512 * 512];          // 2MB   [0]=W' fold, [1]=W1^T, [2]=W2^T, [3]=(Wout+I)^T
__device__ hf g_t2h[(size_t)8192 * 512];   // 8MB   fp16 GEMM2/5 outputs
__device__ float g_field[(size_t)Bn * Mm * Dd]; // 16MB (post-diffuse2 only)

// ------------------------- helpers -----------------------------------------
__device__ __forceinline__ uint32_t smem_u32(const void* p) {
    uint32_t a;
    asm("{ .reg .u64 t; cvta.to.shared.u64 t, %1; cvt.u32.u64 %0, t; }" : "=r"(a) : "l"(p));
    return a;
}
__device__ __forceinline__ uint32_t pack_hf2(float a, float b) {
    __half2 t = __floats2half2_rn(a, b);
    return *reinterpret_cast<uint32_t*>(&t);
}
__device__ __forceinline__ void cp16(uint32_t dst, const void* src) {
    asm volatile("cp.async.cg.shared.global [%0], [%1], 16;" :: "r"(dst), "l"(src));
}
__device__ __forceinline__ void cp_commit() {
    asm volatile("cp.async.commit_group;");
}
__device__ __forceinline__ void cp_wait1() {
    asm volatile("cp.async.wait_group 1;");
}
__device__ __forceinline__ void ldm_x4(uint32_t* r, uint32_t a) {
    asm volatile("ldmatrix.sync.aligned.m8n8.x4.shared.b16 {%0,%1,%2,%3}, [%4];"
                 : "=r"(r[0]), "=r"(r[1]), "=r"(r[2]), "=r"(r[3]) : "r"(a));
}
__device__ __forceinline__ void mma_f16(float* c, const uint32_t* a, const uint32_t* b) {
    asm volatile(
        "mma.sync.aligned.m16n8k16.row.col.f32.f16.f16.f32 "
        "{%0,%1,%2,%3}, {%4,%5,%6,%7}, {%8,%9}, {%0,%1,%2,%3};"
        : "+f"(c[0]), "+f"(c[1]), "+f"(c[2]), "+f"(c[3])
        : "r"(a[0]), "r"(a[1]), "r"(a[2]), "r"(a[3]), "r"(b[0]), "r"(b[1]));
}

// ------------------------- HMMA GEMM (fp16, single-pass, 2-stage) -----------
#define STAGE_B 32768u
#define SMEM_SZ (2 * 32768)

template <bool GELU, bool RESH>
__global__ __launch_bounds__(256, 2)
void k_gemm_mma(const hf* __restrict__ A, size_t aRS, size_t aBS,
                const hf* __restrict__ B, size_t bRS, size_t bBS,
                const float* __restrict__ bias, const hf* __restrict__ resph,
                hf* __restrict__ Ch, size_t cBS, int Kdim)
{
    extern __shared__ char smem[];
    const uint32_t sb = smem_u32(smem);
    const int t = threadIdx.x;
    const int wid = t >> 5;
    const int lane = t & 31;
    const int warp_m = wid & 1;
    const int warp_n = wid >> 1;

    const int m0 = blockIdx.x * 128;
    const int n0 = blockIdx.y * 128;
    const int z = blockIdx.z;

    const hf* pA = A + (size_t)z * aBS;
    const hf* pB = B + (size_t)z * bBS;

    const int NC = Kdim >> 6;

    auto load_chunk = [&](int c) {
        const uint32_t buf = sb + (uint32_t)(c & 1) * STAGE_B;
        const int k0 = c << 6;
#pragma unroll
        for (int i = 0; i < 4; i++) {
            int id = t + i * 256;
            int row = id >> 3;
            int seg = id & 7;
            uint32_t soff = (uint32_t)row * 128 + (uint32_t)((seg * 16) ^ ((row & 7) << 4));
            cp16(buf + soff,         pA + (size_t)(m0 + row) * aRS + k0 + seg * 8);
            cp16(buf + 16384 + soff, pB + (size_t)(n0 + row) * bRS + k0 + seg * 8);
        }
    };

    load_chunk(0); cp_commit();
    if (NC > 1) { load_chunk(1); cp_commit(); }

    const int rowA = warp_m * 64 + (lane & 15);
    const uint32_t maskA = (uint32_t)(rowA & 7) << 4;
    const uint32_t kbA = (uint32_t)(lane >> 4) * 16;
    const int rowB = warp_n * 32 + ((lane >> 4) & 1) * 8 + (lane & 7);
    const uint32_t maskB = (uint32_t)(lane & 7) << 4;
    const uint32_t kbB = (uint32_t)((lane >> 3) & 1) * 16;

    float acc[4][4][4] = {};

    for (int c = 0; c < NC; c++) {
        cp_wait1();
        __syncthreads();
        const uint32_t buf = sb + (uint32_t)(c & 1) * STAGE_B;
        const uint32_t aBase = buf + (uint32_t)rowA * 128;
        const uint32_t bBase = buf + 16384 + (uint32_t)rowB * 128;

#pragma unroll
        for (int k16 = 0; k16 < 4; k16++) {
            const uint32_t koffA = ((uint32_t)k16 * 32 + kbA) ^ maskA;
            const uint32_t koffB = ((uint32_t)k16 * 32 + kbB) ^ maskB;
            uint32_t ah[4][4], bh[4][2];
#pragma unroll
            for (int mi = 0; mi < 4; mi++)
                ldm_x4(ah[mi], aBase + mi * 2048 + koffA);
#pragma unroll
            for (int n4 = 0; n4 < 2; n4++) {
                uint32_t br[4];
                ldm_x4(br, bBase + n4 * 2048 + koffB);
                bh[n4 * 2 + 0][0] = br[0]; bh[n4 * 2 + 0][1] = br[1];
                bh[n4 * 2 + 1][0] = br[2]; bh[n4 * 2 + 1][1] = br[3];
            }
#pragma unroll
            for (int mi = 0; mi < 4; mi++)
#pragma unroll
                for (int ni = 0; ni < 4; ni++)
                    mma_f16(acc[mi][ni], ah[mi], bh[ni]);
        }
        __syncthreads();
        if (c + 2 < NC) load_chunk(c + 2);
        cp_commit();
    }

    const int rbase = m0 + warp_m * 64 + (lane >> 2);
    const int cbase = n0 + warp_n * 32 + (lane & 3) * 2;
#pragma unroll
    for (int mi = 0; mi < 4; mi++) {
#pragma unroll
        for (int half = 0; half < 2; half++) {
            const int row = rbase + mi * 16 + half * 8;
#pragma unroll
            for (int ni = 0; ni < 4; ni++) {
                const int col = cbase + ni * 8;
                float v0 = acc[mi][ni][half * 2 + 0];
                float v1 = acc[mi][ni][half * 2 + 1];
                if (bias) {
                    v0 += __ldg(&bias[col]);
                    v1 += __ldg(&bias[col + 1]);
                }
                if (GELU) {
                    float x3 = v0 * v0 * v0;
                    v0 = 0.5f * v0 * (1.0f + tanhf(0.7978845608028654f * (v0 + 0.044715f * x3)));
                    x3 = v1 * v1 * v1;
                    v1 = 0.5f * v1 * (1.0f + tanhf(0.7978845608028654f * (v1 + 0.044715f * x3)));
                }
                const size_t o = (size_t)z * cBS + (size_t)row * 512 + col;
                if (RESH) {
                    uint32_t rv = *(const uint32_t*)(resph + o);
                    __half2 rh = *reinterpret_cast<__half2*>(&rv);
                    v0 += __half2float(rh.x);
                    v1 += __half2float(rh.y);
                }
                *(uint32_t*)(Ch + o) = pack_hf2(v0, v1);
            }
        }
    }
}

// ------------------------- fused prep (single launch) ----------------------
__global__ __launch_bounds__(256)
void k_prep(const float* __restrict__ w_int, const float* __restrict__ alpha,
            const float* __restrict__ W1, const float* __restrict__ W2,
            const float* __restrict__ Wout,
            const float* __restrict__ emb, const float* __restrict__ pos,
            const float* __restrict__ sigma,
            hf* __restrict__ wh, hf* __restrict__ ebh, hf* __restrict__ kh)
{
    const int t = threadIdx.x;
    const int blk = blockIdx.x;
    if (blk < 1024) {
        const int z = blk >> 8;
        const int xy = blk & 255;
        if (z < 3) {
            __shared__ float tileW[32][33];
            const int tx = t & 31, ty = t >> 5;
            const int c0 = (xy & 15) * 32, r0 = (xy >> 4) * 32;
            const float* src = (z == 0) ? W1 : (z == 1) ? W2 : Wout;
            hf* dst = wh + (size_t)(z + 1) * 262144;
            const bool addI = (z == 2);
#pragma unroll
            for (int i = 0; i < 4; i++)
                tileW[ty + i * 8][tx] = src[(size_t)(r0 + ty + i * 8) * 512 + c0 + tx];
            __syncthreads();
#pragma unroll
            for (int i = 0; i < 4; i++) {
                float v = tileW[tx][ty + i * 8];
                if (addI && (r0 + tx) == (c0 + ty + i * 8)) v += 1.0f;
                dst[(size_t)(c0 + ty + i * 8) * 512 + r0 + tx] = __float2half_rn(v);
            }
        } else {
            __shared__ float sa[64];
            if (t < 64) sa[t] = alpha[t];
            __syncthreads();
#pragma unroll
            for (int it = 0; it < 4; it++) {
                int idx = xy * 1024 + it * 256 + t;
                int j = idx & 511;
                int i = idx >> 9;
                int k = i >> 6, d = i & 63;
                float s = 0.0f;
#pragma unroll
                for (int h = 0; h < 8; h++)
                    s = fmaf(sa[h * 8 + k], w_int[(size_t)(h * 64 + d) * 512 + j], s);
                wh[(size_t)j * 512 + i] = __float2half_rn(s);
            }
        }
    } else if (blk < 17408) {
        __shared__ float tileE[32][33];
        const int id = blk - 1024;
        const int tx = t & 31, ty = t >> 5;
        const int c0 = (id & 15) * 32;
        const int r0 = ((id >> 4) & 63) * 32;
        const int bz = id >> 10;
        const float* src = emb + (size_t)bz * Nn * Dd;
        hf* dst = ebh + (size_t)bz * Dd * Nn;
#pragma unroll
        for (int i = 0; i < 4; i++)
            tileE[ty + i * 8][tx] = src[(size_t)(r0 + ty + i * 8) * Dd + c0 + tx];
        __syncthreads();
#pragma unroll
        for (int i = 0; i < 4; i++) {
            float v = tileE[tx][ty + i * 8];
            dst[(size_t)(c0 + ty + i * 8) * Nn + r0 + tx] = __float2half_rn(v);
        }
    } else {
        size_t lin = (size_t)(blk - 17408) * 256 + t;
        int t8 = (int)(lin & 255);
        int m = (int)((lin >> 8) & 511);
        int b = (int)(lin >> 17);
        float s = __ldg(sigma);
        float inv = 1.0f / (2.0f * s * s);
        float gm = (float)m * (1.0f / 511.0f);
        const float* pp = pos + (size_t)b * Nn + t8 * 8;
        float4 p0 = *(const float4*)pp;
        float4 p1 = *(const float4*)(pp + 4);
        float d0 = gm - p0.x, d1 = gm - p0.y, d2 = gm - p0.z, d3 = gm - p0.w;
        float d4 = gm - p1.x, d5 = gm - p1.y, d6 = gm - p1.z, d7 = gm - p1.w;
        uint4 o4;
        o4.x = pack_hf2(__expf(-d0 * d0 * inv), __expf(-d1 * d1 * inv));
        o4.y = pack_hf2(__expf(-d2 * d2 * inv), __expf(-d3 * d3 * inv));
        o4.z = pack_hf2(__expf(-d4 * d4 * inv), __expf(-d5 * d5 * inv));
        o4.w = pack_hf2(__expf(-d6 * d6 * inv), __expf(-d7 * d7 * inv));
        *(uint4*)(kh + ((size_t)b * 512 + m) * 2048 + t8 * 8) = o4;
    }
}

// ------------------------- single-pass composed diffusion -------------------
// (I + aL)^3 applied as one 7-point stencil (interior); exact 3-step local
// simulation for the 3 boundary rows at each end (Neumann edge padding).
template <bool F32OUT, bool HOUT>
__global__ __launch_bounds__(256)
void k_diffuse1p(const hf* __restrict__ in, float* __restrict__ out,
                 const float* __restrict__ coef, hf* __restrict__ oh)
{
    __shared__ float s[512 * 8];
    const int t = threadIdx.x;
    const int b = blockIdx.x >> 6;
    const int d0 = (blockIdx.x & 63) * 8;
    const int dl = (t & 3) * 2;
    const int mb = t >> 2;
    const size_t gbase = ((size_t)b * Mm) * Dd + d0 + dl;
    const float a0 = DT_C * __ldg(&coef[d0 + dl]);
    const float a1 = DT_C * __ldg(&coef[d0 + dl + 1]);

    // composed interior stencil weights per channel
    const float a0s = a0 * a0, a1s = a1 * a1;
    const float w3a = a0s * a0,                 w3b = a1s * a1;
    const float w2a = 3.f * a0s - 6.f * w3a,    w2b = 3.f * a1s - 6.f * w3b;
    const float w1a = 3.f * a0 - 12.f * a0s + 15.f * w3a;
    const float w1b = 3.f * a1 - 12.f * a1s + 15.f * w3b;
    const float w0a = 1.f - 6.f * a0 + 18.f * a0s - 20.f * w3a;
    const float w0b = 1.f - 6.f * a1 + 18.f * a1s - 20.f * w3b;

#pragma unroll
    for (int i = 0; i < 8; i++) {
        int m = mb + i * 64;
        uint32_t v = *(const uint32_t*)(in + gbase + (size_t)m * Dd);
        __half2 h = *reinterpret_cast<__half2*>(&v);
        s[m * 8 + dl]     = __half2float(h.x);
        s[m * 8 + dl + 1] = __half2float(h.y);
    }
    __syncthreads();

#pragma unroll
    for (int i = 0; i < 8; i++) {
        int m = mb + i * 64;
        int idx = m * 8 + dl;
        float r0, r1;
        if (m >= 3 && m <= 508) {
            r0 = w0a * s[idx]
               + w1a * (s[idx - 8] + s[idx + 8])
               + w2a * (s[idx - 16] + s[idx + 16])
               + w3a * (s[idx - 24] + s[idx + 24]);
            r1 = w0b * s[idx + 1]
               + w1b * (s[idx - 7] + s[idx + 9])
               + w2b * (s[idx - 15] + s[idx + 17])
               + w3b * (s[idx - 23] + s[idx + 25]);
        } else if (m < 3) {
            // exact 3-step simulation on rows 0..5 (left Neumann)
            float f0[6], f1[6];
#pragma unroll
            for (int k = 0; k < 6; k++) {
                f0[k] = s[k * 8 + dl];
                f1[k] = s[k * 8 + dl + 1];
            }
#pragma unroll
            for (int st = 0; st < 3; st++) {
                float p0 = f0[0], p1 = f1[0];
#pragma unroll
                for (int k = 0; k < 5; k++) {
                    if (k <= 4 - st) {
                        float c0v = f0[k], c1v = f1[k];
                        f0[k] = fmaf(a0, p0 - 2.f * c0v + f0[k + 1], c0v);
                        f1[k] = fmaf(a1, p1 - 2.f * c1v + f1[k + 1], c1v);
                        p0 = c0v; p1 = c1v;
                    }
                }
            }
            r0 = f0[m]; r1 = f1[m];
        } else {
            // exact 3-step simulation on rows 506..511 (right Neumann)
            float f0[6], f1[6];
#pragma unroll
            for (int k = 0; k < 6; k++) {
                f0[k] = s[(506 + k) * 8 + dl];
                f1[k] = s[(506 + k) * 8 + dl + 1];
            }
#pragma unroll
            for (int st = 0; st < 3; st++) {
                float p0 = f0[5], p1 = f1[5];
#pragma unroll
                for (int k = 5; k >= 1; k--) {
                    if (k >= 1 + st) {
                        float c0v = f0[k], c1v = f1[k];
                        f0[k] = fmaf(a0, f0[k - 1] - 2.f * c0v + p0, c0v);
                        f1[k] = fmaf(a1, f1[k - 1] - 2.f * c1v + p1, c1v);
                        p0 = c0v; p1 = c1v;
                    }
                }
            }
            r0 = f0[m - 506]; r1 = f1[m - 506];
        }
        size_t g = gbase + (size_t)m * Dd;
        if (F32OUT) *(float2*)(out + g) = make_float2(r0, r1);
        if (HOUT)   *(uint32_t*)(oh + g) = pack_hf2(r0, r1);
    }
}

// sample + residual + LN1 -> fp16 (enh)
__global__ __launch_bounds__(128)
void k_sample_ln(const float* __restrict__ pos, const float* __restrict__ emb,
                 const float* __restrict__ field,
                 const float* __restrict__ gam, const float* __restrict__ bet,
                 hf* __restrict__ oh)
{
    __shared__ float ssum[4], ssq[4], sstat[2];
    int row = blockIdx.x;
    int b = row >> 11;
    float p = __ldg(&pos[row]);
    float u = fminf(fmaxf(p, 0.0f), 1.0f) * (float)(Mm - 1);
    int i0 = (int)u;
    if (i0 > Mm - 2) i0 = Mm - 2;
    float w = u - (float)i0;

    const float* f0 = field + ((size_t)b * Mm + i0) * Dd;
    int t = threadIdx.x;
    int d0 = t * 4;
    float4 a = *(const float4*)(f0 + d0);
    float4 bb = *(const float4*)(f0 + Dd + d0);
    float4 e = *(const float4*)(emb + (size_t)row * Dd + d0);
    float x[4];
    x[0] = fmaf(w, bb.x - a.x, a.x) + e.x;
    x[1] = fmaf(w, bb.y - a.y, a.y) + e.y;
    x[2] = fmaf(w, bb.z - a.z, a.z) + e.z;
    x[3] = fmaf(w, bb.w - a.w, a.w) + e.w;
    float sum = x[0] + x[1] + x[2] + x[3];
    float sq = fmaf(x[0], x[0], fmaf(x[1], x[1], fmaf(x[2], x[2], x[3] * x[3])));
#pragma unroll
    for (int o = 16; o > 0; o >>= 1) {
        sum += __shfl_down_sync(0xffffffffu, sum, o);
        sq += __shfl_down_sync(0xffffffffu, sq, o);
    }
    int wd = t >> 5, ln = t & 31;
    if (ln == 0) { ssum[wd] = sum; ssq[wd] = sq; }
    __syncthreads();
    if (t == 0) {
        float S = ssum[0] + ssum[1] + ssum[2] + ssum[3];
        float Q = ssq[0] + ssq[1] + ssq[2] + ssq[3];
        float mu = S * (1.0f / Dd);
        float var = Q * (1.0f / Dd) - mu * mu;
        sstat[0] = mu;
        sstat[1] = rsqrtf(var + 1e-5f);
    }
    __syncthreads();
    float mu = sstat[0], inv = sstat[1];
    float4 g = *(const float4*)(gam + d0);
    float4 be = *(const float4*)(bet + d0);
    float y0 = (x[0] - mu) * inv * g.x + be.x;
    float y1 = (x[1] - mu) * inv * g.y + be.y;
    float y2 = (x[2] - mu) * inv * g.z + be.z;
    float y3 = (x[3] - mu) * inv * g.w + be.w;
    size_t o = (size_t)row * Dd + d0;
    uint2 hh;
    hh.x = pack_hf2(y0, y1); hh.y = pack_hf2(y2, y3);
    *(uint2*)(oh + o) = hh;
}

// final LN2: reads fp16 pre-LN (residual folded into Wout+I), writes f32 out
__global__ __launch_bounds__(128)
void k_ln2(const hf* __restrict__ pre, const float* __restrict__ gam,
           const float* __restrict__ bet, float* __restrict__ out)
{
    __shared__ float ssum[4], ssq[4], sstat[2];
    int row = blockIdx.x;
    int t = threadIdx.x;
    int d0 = t * 4;
    size_t o = (size_t)row * Dd + d0;
    uint2 hv = *(const uint2*)(pre + o);
    __half2 h01 = *reinterpret_cast<__half2*>(&hv.x);
    __half2 h23 = *reinterpret_cast<__half2*>(&hv.y);
    float x[4] = {__half2float(h01.x), __half2float(h01.y),
                  __half2float(h23.x), __half2float(h23.y)};
    float sum = x[0] + x[1] + x[2] + x[3];
    float sq = fmaf(x[0], x[0], fmaf(x[1], x[1], fmaf(x[2], x[2], x[3] * x[3])));
#pragma unroll
    for (int s = 16; s > 0; s >>= 1) {
        sum += __shfl_down_sync(0xffffffffu, sum, s);
        sq += __shfl_down_sync(0xffffffffu, sq, s);
    }
    int wd = t >> 5, ln = t & 31;
    if (ln == 0) { ssum[wd] = sum; ssq[wd] = sq; }
    __syncthreads();
    if (t == 0) {
        float S = ssum[0] + ssum[1] + ssum[2] + ssum[3];
        float Q = ssq[0] + ssq[1] + ssq[2] + ssq[3];
        float mu = S * (1.0f / Dd);
        float var = Q * (1.0f / Dd) - mu * mu;
        sstat[0] = mu;
        sstat[1] = rsqrtf(var + 1e-5f);
    }
    __syncthreads();
    float mu = sstat[0], inv = sstat[1];
    float4 g = *(const float4*)(gam + d0);
    float4 be = *(const float4*)(bet + d0);
    *(float4*)(out + o) = make_float4(
        (x[0] - mu) * inv * g.x + be.x, (x[1] - mu) * inv * g.y + be.y,
        (x[2] - mu) * inv * g.z + be.z, (x[3] - mu) * inv * g.w + be.w);
}

// ---------------------------------------------------------------------------
extern "C" void kernel_launch(void* const* d_in, const int* in_sizes, int n_in,
                              void* d_out, int out_size)
{
    const float* emb   = (const float*)d_in[0];
    const float* pos   = (const float*)d_in[1];
    const float* sigma = (const float*)d_in[2];
    const float* alpha = (const float*)d_in[3];
    const float* w_int = (const float*)d_in[4];
    const float* b_int = (const float*)d_in[5];
    const float* dcoef = (const float*)d_in[6];
    const float* W1    = (const float*)d_in[7];
    const float* b1    = (const float*)d_in[8];
    const float* W2    = (const float*)d_in[9];
    const float* b2    = (const float*)d_in[10];
    const float* ecoef = (const float*)d_in[11];
    const float* ln1g  = (const float*)d_in[12];
    const float* ln1b  = (const float*)d_in[13];
    const float* Wout  = (const float*)d_in[14];
    const float* bout  = (const float*)d_in[15];
    const float* ln2g  = (const float*)d_in[16];
    const float* ln2b  = (const float*)d_in[17];
    float* out = (float*)d_out;

    hf *h1, *h2, *ebh, *wh, *t2h;
    float *field;
    cudaGetSymbolAddress((void**)&h1, g_h1);
    cudaGetSymbolAddress((void**)&h2, g_h2);
    cudaGetSymbolAddress((void**)&ebh, g_ebh);
    cudaGetSymbolAddress((void**)&wh, g_wh);
    cudaGetSymbolAddress((void**)&t2h, g_t2h);
    cudaGetSymbolAddress((void**)&field, g_field);

    cudaFuncSetAttribute(k_gemm_mma<false, false>,
                         cudaFuncAttributeMaxDynamicSharedMemorySize, SMEM_SZ);
    cudaFuncSetAttribute(k_gemm_mma<false, true>,
                         cudaFuncAttributeMaxDynamicSharedMemorySize, SMEM_SZ);
    cudaFuncSetAttribute(k_gemm_mma<true, false>,
                         cudaFuncAttributeMaxDynamicSharedMemorySize, SMEM_SZ);

    // 0) fused prep: weights (fold W', W1^T, W2^T, (Wout+I)^T), embT, K-RBF->h1
    k_prep<<<25600, 256>>>(w_int, alpha, W1, W2, Wout, emb, pos, sigma,
                           wh, ebh, h1);

    // 1) field(fp16) = K @ emb^T' -> h2    [batched, Kdim=2048]
    k_gemm_mma<false, false><<<dim3(4, 4, 16), 256, SMEM_SZ>>>(
        h1, 2048, (size_t)512 * 2048,
        ebh, 2048, (size_t)512 * 2048,
        nullptr, nullptr, h2, (size_t)512 * 512, 2048);

    // 2) t2h = field + field @ W' + b_int   (fp16 out, fp16 residual)
    k_gemm_mma<false, true><<<dim3(64, 4, 1), 256, SMEM_SZ>>>(
        h2, 512, 0, wh + 0 * 262144, 512, 0,
        b_int, h2, t2h, 0, 512);

    // 3) diffusion x3 (dcoef, single composed pass): t2h -> h2 (fp16)
    k_diffuse1p<false, true><<<Bn * 64, 256>>>(t2h, nullptr, dcoef, h2);

    // 4) gelu(field @ W1 + b1) -> h1 (fp16)
    k_gemm_mma<true, false><<<dim3(64, 4, 1), 256, SMEM_SZ>>>(
        h2, 512, 0, wh + 1 * 262144, 512, 0,
        b1, nullptr, h1, 0, 512);

    // 5) t2h = field(h2) + gelu @ W2 + b2   (fp16 out, fp16 residual)
    k_gemm_mma<false, true><<<dim3(64, 4, 1), 256, SMEM_SZ>>>(
        h1, 512, 0, wh + 2 * 262144, 512, 0,
        b2, h2, t2h, 0, 512);

    // 6) diffusion x3 (ecoef, single composed pass): t2h -> field (f32)
    k_diffuse1p<true, false><<<Bn * 64, 256>>>(t2h, field, ecoef, nullptr);

    // 7) enh = LN1(sample(field) + emb) -> h1 (fp16)
    k_sample_ln<<<Bn * Nn, 128>>>(pos, emb, field, ln1g, ln1b, h1);

    // 8) preLN2 = enh @ (Wout + I) + bout -> ebh (fp16; residual folded)
    k_gemm_mma<false, false><<<dim3(256, 4, 1), 256, SMEM_SZ>>>(
        h1, 512, 0, wh + 3 * 262144, 512, 0,
        bout, nullptr, ebh, 0, 512);

    // 9) out = LN2(preLN2)
    k_ln2<<<Bn * Nn, 128>>>(ebh, ln2g, ln2b, out);
}

// round 17
// speedup vs baseline: 1.1528x; 1.0070x over previous
#include <cuda_runtime.h>
#include <cuda_fp16.h>
#include <math.h>
#include <stdint.h>

#define Bn 16
#define Nn 2048
#define Dd 512
#define Mm 512
#define DT_C 0.01f

typedef __half hf;

// ------------------------- device scratch (no runtime alloc) ---------------
__device__ hf g_h1[(size_t)32768 * 512];   // 32MB  (K-RBF A / gelu / enh)
__device__ hf g_h2[(size_t)8192 * 512];    // 8MB   (field fp16)
__device__ hf g_ebh[(size_t)Bn * Dd * Nn]; // 32MB  embT [b,d,t]; later pre-LN2 fp16
__device__ hf g_wh[4][512 * 512];          // 2MB   [0]=W' fold, [1]=W1^T, [2]=W2^T, [3]=(Wout+I)^T
__device__ hf g_t2h[(size_t)8192 * 512];   // 8MB   fp16 GEMM2/5 outputs
__device__ float g_field[(size_t)Bn * Mm * Dd]; // 16MB (post-diffuse2 only)

// ------------------------- helpers -----------------------------------------
__device__ __forceinline__ uint32_t smem_u32(const void* p) {
    uint32_t a;
    asm("{ .reg .u64 t; cvta.to.shared.u64 t, %1; cvt.u32.u64 %0, t; }" : "=r"(a) : "l"(p));
    return a;
}
__device__ __forceinline__ uint32_t pack_hf2(float a, float b) {
    __half2 t = __floats2half2_rn(a, b);
    return *reinterpret_cast<uint32_t*>(&t);
}
__device__ __forceinline__ void unpack8(uint4 v, float* f) {
    __half2 h0 = *reinterpret_cast<__half2*>(&v.x);
    __half2 h1 = *reinterpret_cast<__half2*>(&v.y);
    __half2 h2 = *reinterpret_cast<__half2*>(&v.z);
    __half2 h3 = *reinterpret_cast<__half2*>(&v.w);
    f[0] = __half2float(h0.x); f[1] = __half2float(h0.y);
    f[2] = __half2float(h1.x); f[3] = __half2float(h1.y);
    f[4] = __half2float(h2.x); f[5] = __half2float(h2.y);
    f[6] = __half2float(h3.x); f[7] = __half2float(h3.y);
}
__device__ __forceinline__ void cp16(uint32_t dst, const void* src) {
    asm volatile("cp.async.cg.shared.global [%0], [%1], 16;" :: "r"(dst), "l"(src));
}
__device__ __forceinline__ void cp_commit() {
    asm volatile("cp.async.commit_group;");
}
__device__ __forceinline__ void cp_wait1() {
    asm volatile("cp.async.wait_group 1;");
}
__device__ __forceinline__ void ldm_x4(uint32_t* r, uint32_t a) {
    asm volatile("ldmatrix.sync.aligned.m8n8.x4.shared.b16 {%0,%1,%2,%3}, [%4];"
                 : "=r"(r[0]), "=r"(r[1]), "=r"(r[2]), "=r"(r[3]) : "r"(a));
}
__device__ __forceinline__ void mma_f16(float* c, const uint32_t* a, const uint32_t* b) {
    asm volatile(
        "mma.sync.aligned.m16n8k16.row.col.f32.f16.f16.f32 "
        "{%0,%1,%2,%3}, {%4,%5,%6,%7}, {%8,%9}, {%0,%1,%2,%3};"
        : "+f"(c[0]), "+f"(c[1]), "+f"(c[2]), "+f"(c[3])
        : "r"(a[0]), "r"(a[1]), "r"(a[2]), "r"(a[3]), "r"(b[0]), "r"(b[1]));
}

// ------------------------- HMMA GEMM (fp16, single-pass, 2-stage) -----------
#define STAGE_B 32768u
#define SMEM_SZ (2 * 32768)

template <bool GELU, bool RESH>
__global__ __launch_bounds__(256, 2)
void k_gemm_mma(const hf* __restrict__ A, size_t aRS, size_t aBS,
                const hf* __restrict__ B, size_t bRS, size_t bBS,
                const float* __restrict__ bias, const hf* __restrict__ resph,
                hf* __restrict__ Ch, size_t cBS, int Kdim)
{
    extern __shared__ char smem[];
    const uint32_t sb = smem_u32(smem);
    const int t = threadIdx.x;
    const int wid = t >> 5;
    const int lane = t & 31;
    const int warp_m = wid & 1;
    const int warp_n = wid >> 1;

    const int m0 = blockIdx.x * 128;
    const int n0 = blockIdx.y * 128;
    const int z = blockIdx.z;

    const hf* pA = A + (size_t)z * aBS;
    const hf* pB = B + (size_t)z * bBS;

    const int NC = Kdim >> 6;

    auto load_chunk = [&](int c) {
        const uint32_t buf = sb + (uint32_t)(c & 1) * STAGE_B;
        const int k0 = c << 6;
#pragma unroll
        for (int i = 0; i < 4; i++) {
            int id = t + i * 256;
            int row = id >> 3;
            int seg = id & 7;
            uint32_t soff = (uint32_t)row * 128 + (uint32_t)((seg * 16) ^ ((row & 7) << 4));
            cp16(buf + soff,         pA + (size_t)(m0 + row) * aRS + k0 + seg * 8);
            cp16(buf + 16384 + soff, pB + (size_t)(n0 + row) * bRS + k0 + seg * 8);
        }
    };

    load_chunk(0); cp_commit();
    if (NC > 1) { load_chunk(1); cp_commit(); }

    const int rowA = warp_m * 64 + (lane & 15);
    const uint32_t maskA = (uint32_t)(rowA & 7) << 4;
    const uint32_t kbA = (uint32_t)(lane >> 4) * 16;
    const int rowB = warp_n * 32 + ((lane >> 4) & 1) * 8 + (lane & 7);
    const uint32_t maskB = (uint32_t)(lane & 7) << 4;
    const uint32_t kbB = (uint32_t)((lane >> 3) & 1) * 16;

    float acc[4][4][4] = {};

    for (int c = 0; c < NC; c++) {
        cp_wait1();
        __syncthreads();
        const uint32_t buf = sb + (uint32_t)(c & 1) * STAGE_B;
        const uint32_t aBase = buf + (uint32_t)rowA * 128;
        const uint32_t bBase = buf + 16384 + (uint32_t)rowB * 128;

#pragma unroll
        for (int k16 = 0; k16 < 4; k16++) {
            const uint32_t koffA = ((uint32_t)k16 * 32 + kbA) ^ maskA;
            const uint32_t koffB = ((uint32_t)k16 * 32 + kbB) ^ maskB;
            uint32_t ah[4][4], bh[4][2];
#pragma unroll
            for (int mi = 0; mi < 4; mi++)
                ldm_x4(ah[mi], aBase + mi * 2048 + koffA);
#pragma unroll
            for (int n4 = 0; n4 < 2; n4++) {
                uint32_t br[4];
                ldm_x4(br, bBase + n4 * 2048 + koffB);
                bh[n4 * 2 + 0][0] = br[0]; bh[n4 * 2 + 0][1] = br[1];
                bh[n4 * 2 + 1][0] = br[2]; bh[n4 * 2 + 1][1] = br[3];
            }
#pragma unroll
            for (int mi = 0; mi < 4; mi++)
#pragma unroll
                for (int ni = 0; ni < 4; ni++)
                    mma_f16(acc[mi][ni], ah[mi], bh[ni]);
        }
        __syncthreads();
        if (c + 2 < NC) load_chunk(c + 2);
        cp_commit();
    }

    const int rbase = m0 + warp_m * 64 + (lane >> 2);
    const int cbase = n0 + warp_n * 32 + (lane & 3) * 2;
#pragma unroll
    for (int mi = 0; mi < 4; mi++) {
#pragma unroll
        for (int half = 0; half < 2; half++) {
            const int row = rbase + mi * 16 + half * 8;
#pragma unroll
            for (int ni = 0; ni < 4; ni++) {
                const int col = cbase + ni * 8;
                float v0 = acc[mi][ni][half * 2 + 0];
                float v1 = acc[mi][ni][half * 2 + 1];
                if (bias) {
                    v0 += __ldg(&bias[col]);
                    v1 += __ldg(&bias[col + 1]);
                }
                if (GELU) {
                    float x3 = v0 * v0 * v0;
                    v0 = 0.5f * v0 * (1.0f + tanhf(0.7978845608028654f * (v0 + 0.044715f * x3)));
                    x3 = v1 * v1 * v1;
                    v1 = 0.5f * v1 * (1.0f + tanhf(0.7978845608028654f * (v1 + 0.044715f * x3)));
                }
                const size_t o = (size_t)z * cBS + (size_t)row * 512 + col;
                if (RESH) {
                    uint32_t rv = *(const uint32_t*)(resph + o);
                    __half2 rh = *reinterpret_cast<__half2*>(&rv);
                    v0 += __half2float(rh.x);
                    v1 += __half2float(rh.y);
                }
                *(uint32_t*)(Ch + o) = pack_hf2(v0, v1);
            }
        }
    }
}

// ------------------------- fused prep (single launch) ----------------------
__global__ __launch_bounds__(256)
void k_prep(const float* __restrict__ w_int, const float* __restrict__ alpha,
            const float* __restrict__ W1, const float* __restrict__ W2,
            const float* __restrict__ Wout,
            const float* __restrict__ emb, const float* __restrict__ pos,
            const float* __restrict__ sigma,
            hf* __restrict__ wh, hf* __restrict__ ebh, hf* __restrict__ kh)
{
    const int t = threadIdx.x;
    const int blk = blockIdx.x;
    if (blk < 1024) {
        const int z = blk >> 8;
        const int xy = blk & 255;
        if (z < 3) {
            __shared__ float tileW[32][33];
            const int tx = t & 31, ty = t >> 5;
            const int c0 = (xy & 15) * 32, r0 = (xy >> 4) * 32;
            const float* src = (z == 0) ? W1 : (z == 1) ? W2 : Wout;
            hf* dst = wh + (size_t)(z + 1) * 262144;
            const bool addI = (z == 2);
#pragma unroll
            for (int i = 0; i < 4; i++)
                tileW[ty + i * 8][tx] = src[(size_t)(r0 + ty + i * 8) * 512 + c0 + tx];
            __syncthreads();
#pragma unroll
            for (int i = 0; i < 4; i++) {
                float v = tileW[tx][ty + i * 8];
                if (addI && (r0 + tx) == (c0 + ty + i * 8)) v += 1.0f;
                dst[(size_t)(c0 + ty + i * 8) * 512 + r0 + tx] = __float2half_rn(v);
            }
        } else {
            __shared__ float sa[64];
            if (t < 64) sa[t] = alpha[t];
            __syncthreads();
#pragma unroll
            for (int it = 0; it < 4; it++) {
                int idx = xy * 1024 + it * 256 + t;
                int j = idx & 511;
                int i = idx >> 9;
                int k = i >> 6, d = i & 63;
                float s = 0.0f;
#pragma unroll
                for (int h = 0; h < 8; h++)
                    s = fmaf(sa[h * 8 + k], w_int[(size_t)(h * 64 + d) * 512 + j], s);
                wh[(size_t)j * 512 + i] = __float2half_rn(s);
            }
        }
    } else if (blk < 17408) {
        __shared__ float tileE[32][33];
        const int id = blk - 1024;
        const int tx = t & 31, ty = t >> 5;
        const int c0 = (id & 15) * 32;
        const int r0 = ((id >> 4) & 63) * 32;
        const int bz = id >> 10;
        const float* src = emb + (size_t)bz * Nn * Dd;
        hf* dst = ebh + (size_t)bz * Dd * Nn;
#pragma unroll
        for (int i = 0; i < 4; i++)
            tileE[ty + i * 8][tx] = src[(size_t)(r0 + ty + i * 8) * Dd + c0 + tx];
        __syncthreads();
#pragma unroll
        for (int i = 0; i < 4; i++) {
            float v = tileE[tx][ty + i * 8];
            dst[(size_t)(c0 + ty + i * 8) * Nn + r0 + tx] = __float2half_rn(v);
        }
    } else {
        size_t lin = (size_t)(blk - 17408) * 256 + t;
        int t8 = (int)(lin & 255);
        int m = (int)((lin >> 8) & 511);
        int b = (int)(lin >> 17);
        float s = __ldg(sigma);
        float inv = 1.0f / (2.0f * s * s);
        float gm = (float)m * (1.0f / 511.0f);
        const float* pp = pos + (size_t)b * Nn + t8 * 8;
        float4 p0 = *(const float4*)pp;
        float4 p1 = *(const float4*)(pp + 4);
        float d0 = gm - p0.x, d1 = gm - p0.y, d2 = gm - p0.z, d3 = gm - p0.w;
        float d4 = gm - p1.x, d5 = gm - p1.y, d6 = gm - p1.z, d7 = gm - p1.w;
        uint4 o4;
        o4.x = pack_hf2(__expf(-d0 * d0 * inv), __expf(-d1 * d1 * inv));
        o4.y = pack_hf2(__expf(-d2 * d2 * inv), __expf(-d3 * d3 * inv));
        o4.z = pack_hf2(__expf(-d4 * d4 * inv), __expf(-d5 * d5 * inv));
        o4.w = pack_hf2(__expf(-d6 * d6 * inv), __expf(-d7 * d7 * inv));
        *(uint4*)(kh + ((size_t)b * 512 + m) * 2048 + t8 * 8) = o4;
    }
}

// --------------- register-direct composed diffusion (coalesced) ------------
// One thread = 8 contiguous channels of one output row. Interior: 7-point
// composed stencil streamed from 7 coalesced row loads. Boundary rows (m<3,
// m>508): exact 3-step Euler simulation on the 6-row window.
// Total threads = Bn*Mm*64 = 524288 -> grid 2048 x 256.
template <bool F32OUT, bool HOUT>
__global__ __launch_bounds__(256)
void k_diffuse_reg(const hf* __restrict__ in, float* __restrict__ out,
                   const float* __restrict__ coef, hf* __restrict__ oh)
{
    const int lin = blockIdx.x * 256 + threadIdx.x;  // < 16*512*64
    const int d8 = lin & 63;
    const int m  = (lin >> 6) & 511;
    const int b  = lin >> 15;
    const int dbase = d8 * 8;
    const hf* base = in + ((size_t)b * Mm) * Dd + dbase;

    float a[8];
    {
        float4 c0 = *(const float4*)(coef + dbase);
        float4 c1 = *(const float4*)(coef + dbase + 4);
        a[0] = DT_C * c0.x; a[1] = DT_C * c0.y; a[2] = DT_C * c0.z; a[3] = DT_C * c0.w;
        a[4] = DT_C * c1.x; a[5] = DT_C * c1.y; a[6] = DT_C * c1.z; a[7] = DT_C * c1.w;
    }

    float r[8];
    if (m >= 3 && m <= 508) {
        float w0[8], w1[8], w2[8], w3[8];
#pragma unroll
        for (int j = 0; j < 8; j++) {
            float as = a[j] * a[j];
            w3[j] = as * a[j];
            w2[j] = 3.f * as - 6.f * w3[j];
            w1[j] = 3.f * a[j] - 12.f * as + 15.f * w3[j];
            w0[j] = 1.f - 6.f * a[j] + 18.f * as - 20.f * w3[j];
        }
        float f[8];
#pragma unroll
        for (int j = 0; j < 8; j++) r[j] = 0.f;
        unpack8(*(const uint4*)(base + (size_t)(m - 3) * Dd), f);
#pragma unroll
        for (int j = 0; j < 8; j++) r[j] = fmaf(w3[j], f[j], r[j]);
        unpack8(*(const uint4*)(base + (size_t)(m - 2) * Dd), f);
#pragma unroll
        for (int j = 0; j < 8; j++) r[j] = fmaf(w2[j], f[j], r[j]);
        unpack8(*(const uint4*)(base + (size_t)(m - 1) * Dd), f);
#pragma unroll
        for (int j = 0; j < 8; j++) r[j] = fmaf(w1[j], f[j], r[j]);
        unpack8(*(const uint4*)(base + (size_t)m * Dd), f);
#pragma unroll
        for (int j = 0; j < 8; j++) r[j] = fmaf(w0[j], f[j], r[j]);
        unpack8(*(const uint4*)(base + (size_t)(m + 1) * Dd), f);
#pragma unroll
        for (int j = 0; j < 8; j++) r[j] = fmaf(w1[j], f[j], r[j]);
        unpack8(*(const uint4*)(base + (size_t)(m + 2) * Dd), f);
#pragma unroll
        for (int j = 0; j < 8; j++) r[j] = fmaf(w2[j], f[j], r[j]);
        unpack8(*(const uint4*)(base + (size_t)(m + 3) * Dd), f);
#pragma unroll
        for (int j = 0; j < 8; j++) r[j] = fmaf(w3[j], f[j], r[j]);
    } else if (m < 3) {
        float f[6][8];
#pragma unroll
        for (int k = 0; k < 6; k++)
            unpack8(*(const uint4*)(base + (size_t)k * Dd), f[k]);
#pragma unroll
        for (int st = 0; st < 3; st++) {
            float p[8];
#pragma unroll
            for (int j = 0; j < 8; j++) p[j] = f[0][j];
#pragma unroll
            for (int k = 0; k < 5; k++) {
                if (k <= 4 - st) {
#pragma unroll
                    for (int j = 0; j < 8; j++) {
                        float c = f[k][j];
                        f[k][j] = fmaf(a[j], p[j] - 2.f * c + f[k + 1][j], c);
                        p[j] = c;
                    }
                }
            }
        }
#pragma unroll
        for (int j = 0; j < 8; j++) r[j] = f[m][j];
    } else {
        float f[6][8];
#pragma unroll
        for (int k = 0; k < 6; k++)
            unpack8(*(const uint4*)(base + (size_t)(506 + k) * Dd), f[k]);
#pragma unroll
        for (int st = 0; st < 3; st++) {
            float p[8];
#pragma unroll
            for (int j = 0; j < 8; j++) p[j] = f[5][j];
#pragma unroll
            for (int k = 5; k >= 1; k--) {
                if (k >= 1 + st) {
#pragma unroll
                    for (int j = 0; j < 8; j++) {
                        float c = f[k][j];
                        f[k][j] = fmaf(a[j], f[k - 1][j] - 2.f * c + p[j], c);
                        p[j] = c;
                    }
                }
            }
        }
#pragma unroll
        for (int j = 0; j < 8; j++) r[j] = f[m - 506][j];
    }

    const size_t g = ((size_t)b * Mm + m) * Dd + dbase;
    if (F32OUT) {
        *(float4*)(out + g)     = make_float4(r[0], r[1], r[2], r[3]);
        *(float4*)(out + g + 4) = make_float4(r[4], r[5], r[6], r[7]);
    }
    if (HOUT) {
        uint4 o4;
        o4.x = pack_hf2(r[0], r[1]); o4.y = pack_hf2(r[2], r[3]);
        o4.z = pack_hf2(r[4], r[5]); o4.w = pack_hf2(r[6], r[7]);
        *(uint4*)(oh + g) = o4;
    }
}

// sample + residual + LN1 -> fp16 (enh)
__global__ __launch_bounds__(128)
void k_sample_ln(const float* __restrict__ pos, const float* __restrict__ emb,
                 const float* __restrict__ field,
                 const float* __restrict__ gam, const float* __restrict__ bet,
                 hf* __restrict__ oh)
{
    __shared__ float ssum[4], ssq[4], sstat[2];
    int row = blockIdx.x;
    int b = row >> 11;
    float p = __ldg(&pos[row]);
    float u = fminf(fmaxf(p, 0.0f), 1.0f) * (float)(Mm - 1);
    int i0 = (int)u;
    if (i0 > Mm - 2) i0 = Mm - 2;
    float w = u - (float)i0;

    const float* f0 = field + ((size_t)b * Mm + i0) * Dd;
    int t = threadIdx.x;
    int d0 = t * 4;
    float4 a = *(const float4*)(f0 + d0);
    float4 bb = *(const float4*)(f0 + Dd + d0);
    float4 e = *(const float4*)(emb + (size_t)row * Dd + d0);
    float x[4];
    x[0] = fmaf(w, bb.x - a.x, a.x) + e.x;
    x[1] = fmaf(w, bb.y - a.y, a.y) + e.y;
    x[2] = fmaf(w, bb.z - a.z, a.z) + e.z;
    x[3] = fmaf(w, bb.w - a.w, a.w) + e.w;
    float sum = x[0] + x[1] + x[2] + x[3];
    float sq = fmaf(x[0], x[0], fmaf(x[1], x[1], fmaf(x[2], x[2], x[3] * x[3])));
#pragma unroll
    for (int o = 16; o > 0; o >>= 1) {
        sum += __shfl_down_sync(0xffffffffu, sum, o);
        sq += __shfl_down_sync(0xffffffffu, sq, o);
    }
    int wd = t >> 5, ln = t & 31;
    if (ln == 0) { ssum[wd] = sum; ssq[wd] = sq; }
    __syncthreads();
    if (t == 0) {
        float S = ssum[0] + ssum[1] + ssum[2] + ssum[3];
        float Q = ssq[0] + ssq[1] + ssq[2] + ssq[3];
        float mu = S * (1.0f / Dd);
        float var = Q * (1.0f / Dd) - mu * mu;
        sstat[0] = mu;
        sstat[1] = rsqrtf(var + 1e-5f);
    }
    __syncthreads();
    float mu = sstat[0], inv = sstat[1];
    float4 g = *(const float4*)(gam + d0);
    float4 be = *(const float4*)(bet + d0);
    float y0 = (x[0] - mu) * inv * g.x + be.x;
    float y1 = (x[1] - mu) * inv * g.y + be.y;
    float y2 = (x[2] - mu) * inv * g.z + be.z;
    float y3 = (x[3] - mu) * inv * g.w + be.w;
    size_t o = (size_t)row * Dd + d0;
    uint2 hh;
    hh.x = pack_hf2(y0, y1); hh.y = pack_hf2(y2, y3);
    *(uint2*)(oh + o) = hh;
}

// final LN2: reads fp16 pre-LN (residual folded into Wout+I), writes f32 out
__global__ __launch_bounds__(128)
void k_ln2(const hf* __restrict__ pre, const float* __restrict__ gam,
           const float* __restrict__ bet, float* __restrict__ out)
{
    __shared__ float ssum[4], ssq[4], sstat[2];
    int row = blockIdx.x;
    int t = threadIdx.x;
    int d0 = t * 4;
    size_t o = (size_t)row * Dd + d0;
    uint2 hv = *(const uint2*)(pre + o);
    __half2 h01 = *reinterpret_cast<__half2*>(&hv.x);
    __half2 h23 = *reinterpret_cast<__half2*>(&hv.y);
    float x[4] = {__half2float(h01.x), __half2float(h01.y),
                  __half2float(h23.x), __half2float(h23.y)};
    float sum = x[0] + x[1] + x[2] + x[3];
    float sq = fmaf(x[0], x[0], fmaf(x[1], x[1], fmaf(x[2], x[2], x[3] * x[3])));
#pragma unroll
    for (int s = 16; s > 0; s >>= 1) {
        sum += __shfl_down_sync(0xffffffffu, sum, s);
        sq += __shfl_down_sync(0xffffffffu, sq, s);
    }
    int wd = t >> 5, ln = t & 31;
    if (ln == 0) { ssum[wd] = sum; ssq[wd] = sq; }
    __syncthreads();
    if (t == 0) {
        float S = ssum[0] + ssum[1] + ssum[2] + ssum[3];
        float Q = ssq[0] + ssq[1] + ssq[2] + ssq[3];
        float mu = S * (1.0f / Dd);
        float var = Q * (1.0f / Dd) - mu * mu;
        sstat[0] = mu;
        sstat[1] = rsqrtf(var + 1e-5f);
    }
    __syncthreads();
    float mu = sstat[0], inv = sstat[1];
    float4 g = *(const float4*)(gam + d0);
    float4 be = *(const float4*)(bet + d0);
    *(float4*)(out + o) = make_float4(
        (x[0] - mu) * inv * g.x + be.x, (x[1] - mu) * inv * g.y + be.y,
        (x[2] - mu) * inv * g.z + be.z, (x[3] - mu) * inv * g.w + be.w);
}

// ---------------------------------------------------------------------------
extern "C" void kernel_launch(void* const* d_in, const int* in_sizes, int n_in,
                              void* d_out, int out_size)
{
    const float* emb   = (const float*)d_in[0];
    const float* pos   = (const float*)d_in[1];
    const float* sigma = (const float*)d_in[2];
    const float* alpha = (const float*)d_in[3];
    const float* w_int = (const float*)d_in[4];
    const float* b_int = (const float*)d_in[5];
    const float* dcoef = (const float*)d_in[6];
    const float* W1    = (const float*)d_in[7];
    const float* b1    = (const float*)d_in[8];
    const float* W2    = (const float*)d_in[9];
    const float* b2    = (const float*)d_in[10];
    const float* ecoef = (const float*)d_in[11];
    const float* ln1g  = (const float*)d_in[12];
    const float* ln1b  = (const float*)d_in[13];
    const float* Wout  = (const float*)d_in[14];
    const float* bout  = (const float*)d_in[15];
    const float* ln2g  = (const float*)d_in[16];
    const float* ln2b  = (const float*)d_in[17];
    float* out = (float*)d_out;

    hf *h1, *h2, *ebh, *wh, *t2h;
    float *field;
    cudaGetSymbolAddress((void**)&h1, g_h1);
    cudaGetSymbolAddress((void**)&h2, g_h2);
    cudaGetSymbolAddress((void**)&ebh, g_ebh);
    cudaGetSymbolAddress((void**)&wh, g_wh);
    cudaGetSymbolAddress((void**)&t2h, g_t2h);
    cudaGetSymbolAddress((void**)&field, g_field);

    cudaFuncSetAttribute(k_gemm_mma<false, false>,
                         cudaFuncAttributeMaxDynamicSharedMemorySize, SMEM_SZ);
    cudaFuncSetAttribute(k_gemm_mma<false, true>,
                         cudaFuncAttributeMaxDynamicSharedMemorySize, SMEM_SZ);
    cudaFuncSetAttribute(k_gemm_mma<true, false>,
                         cudaFuncAttributeMaxDynamicSharedMemorySize, SMEM_SZ);

    // 0) fused prep: weights (fold W', W1^T, W2^T, (Wout+I)^T), embT, K-RBF->h1
    k_prep<<<25600, 256>>>(w_int, alpha, W1, W2, Wout, emb, pos, sigma,
                           wh, ebh, h1);

    // 1) field(fp16) = K @ emb^T' -> h2    [batched, Kdim=2048]
    k_gemm_mma<false, false><<<dim3(4, 4, 16), 256, SMEM_SZ>>>(
        h1, 2048, (size_t)512 * 2048,
        ebh, 2048, (size_t)512 * 2048,
        nullptr, nullptr, h2, (size_t)512 * 512, 2048);

    // 2) t2h = field + field @ W' + b_int   (fp16 out, fp16 residual)
    k_gemm_mma<false, true><<<dim3(64, 4, 1), 256, SMEM_SZ>>>(
        h2, 512, 0, wh + 0 * 262144, 512, 0,
        b_int, h2, t2h, 0, 512);

    // 3) diffusion x3 (dcoef, composed single pass): t2h -> h2 (fp16)
    k_diffuse_reg<false, true><<<2048, 256>>>(t2h, nullptr, dcoef, h2);

    // 4) gelu(field @ W1 + b1) -> h1 (fp16)
    k_gemm_mma<true, false><<<dim3(64, 4, 1), 256, SMEM_SZ>>>(
        h2, 512, 0, wh + 1 * 262144, 512, 0,
        b1, nullptr, h1, 0, 512);

    // 5) t2h = field(h2) + gelu @ W2 + b2   (fp16 out, fp16 residual)
    k_gemm_mma<false, true><<<dim3(64, 4, 1), 256, SMEM_SZ>>>(
        h1, 512, 0, wh + 2 * 262144, 512, 0,
        b2, h2, t2h, 0, 512);

    // 6) diffusion x3 (ecoef, composed single pass): t2h -> field (f32)
    k_diffuse_reg<true, false><<<2048, 256>>>(t2h, field, ecoef, nullptr);

    // 7) enh = LN1(sample(field) + emb) -> h1 (fp16)
    k_sample_ln<<<Bn * Nn, 128>>>(pos, emb, field, ln1g, ln1b, h1);

    // 8) preLN2 = enh @ (Wout + I) + bout -> ebh (fp16; residual folded)
    k_gemm_mma<false, false><<<dim3(256, 4, 1), 256, SMEM_SZ>>>(
        h1, 512, 0, wh + 3 * 262144, 512, 0,
        bout, nullptr, ebh, 0, 512);

    // 9) out = LN2(preLN2)
    k_ln2<<<Bn * Nn, 128>>>(ebh, ln2g, ln2b, out);
}